// round 11
// baseline (speedup 1.0000x reference)
#include <cuda_runtime.h>
#include <cuda_fp16.h>
#include <cstdint>

#define BB 128          // batch
#define TT 64           // time steps
#define EE 300          // embed dim
#define HH 2048         // hidden
#define G4 8192         // 4*H

// ---------------- scratch (device globals; no allocation allowed) ----------
__device__ float g_gx2[(size_t)TT * 128 * 128 * 64];   // [t][cb][b][gate*16+hc]
__device__ __half g_w16[(size_t)G4 * HH];              // W_hh fp16
__device__ __half g_ha[BB * HH];                       // hidden state ping
__device__ __half g_hb[BB * HH];                       // hidden state pong
__device__ float g_c2[BB * HH];                        // cell state [cb][b][16]
__device__ float g_part[128][BB * 64];                 // split-K partial (half 1)
__device__ unsigned g_pflag[128];                      // per-cb partial-ready flag
__device__ unsigned g_bar;                             // persistent-kernel barrier

// single dynamic smem symbol shared by all kernels
extern __shared__ __align__(1024) char dyn_smem[];

// ---------------- helpers --------------------------------------------------
__device__ __forceinline__ uint32_t smem_u32(const void* p) {
    return (uint32_t)__cvta_generic_to_shared(p);
}
__device__ __forceinline__ void cp16(uint32_t dst, const void* src) {
    asm volatile("cp.async.cg.shared.global [%0], [%1], 16;\n" ::"r"(dst), "l"(src));
}
__device__ __forceinline__ void cp16z(uint32_t dst, const void* src, int bytes) {
    asm volatile("cp.async.ca.shared.global [%0], [%1], 16, %2;\n" ::"r"(dst), "l"(src), "r"(bytes));
}
__device__ __forceinline__ void cp_commit() { asm volatile("cp.async.commit_group;\n"); }
template <int N> __device__ __forceinline__ void cp_wait() {
    asm volatile("cp.async.wait_group %0;\n" ::"n"(N));
}
__device__ __forceinline__ void mma_fp16(float c[4], const uint32_t a[4], uint32_t b0,
                                         uint32_t b1) {
    asm volatile(
        "mma.sync.aligned.m16n8k16.row.col.f32.f16.f16.f32 "
        "{%0,%1,%2,%3},{%4,%5,%6,%7},{%8,%9},{%0,%1,%2,%3};\n"
        : "+f"(c[0]), "+f"(c[1]), "+f"(c[2]), "+f"(c[3])
        : "r"(a[0]), "r"(a[1]), "r"(a[2]), "r"(a[3]), "r"(b0), "r"(b1));
}
__device__ __forceinline__ void ldsm4(uint32_t r[4], uint32_t addr) {
    asm volatile("ldmatrix.sync.aligned.m8n8.x4.shared.b16 {%0,%1,%2,%3}, [%4];"
                 : "=r"(r[0]), "=r"(r[1]), "=r"(r[2]), "=r"(r[3])
                 : "r"(addr));
}
__device__ __forceinline__ float sigmoidf_(float x) { return 1.0f / (1.0f + __expf(-x)); }

#define SMEM_SWZ128(x) ((x) ^ (((x) >> 3) & 0x70))

// ---------------- init / W convert ------------------------------------------
__global__ void zero_kernel() {
    int i = blockIdx.x * blockDim.x + threadIdx.x;
    if (i < BB * HH) {
        g_ha[i] = __float2half(0.f);
        g_c2[i] = 0.f;
    }
    if (i < 128) g_pflag[i] = 0u;
    if (i == 0) g_bar = 0u;
}

__global__ void wconv_kernel(const float* __restrict__ w) {
    size_t i = ((size_t)blockIdx.x * blockDim.x + threadIdx.x) * 4;
    if (i < (size_t)G4 * HH) {
        float4 v = *reinterpret_cast<const float4*>(w + i);
        g_w16[i] = __float2half(v.x);
        g_w16[i + 1] = __float2half(v.y);
        g_w16[i + 2] = __float2half(v.z);
        g_w16[i + 3] = __float2half(v.w);
    }
}

// ---------------- kernel 1: embedding gather + input projection (tf32 SIMT) -
#define LDA 36
#define XP_STAGE_FLOATS ((128 + 64) * LDA)
#define XP_SMEM_BYTES (2 * XP_STAGE_FLOATS * 4)

__device__ __forceinline__ void compute_block_tf32(const float* __restrict__ As,
                                                   const float* __restrict__ Bs,
                                                   float acc[2][4][4], int wm, int wn, int g,
                                                   int tig) {
#pragma unroll
    for (int k8 = 0; k8 < 32; k8 += 8) {
        uint32_t a[2][4];
#pragma unroll
        for (int mt = 0; mt < 2; mt++) {
            int r = wm + mt * 16;
            a[mt][0] = __float_as_uint(As[(r + g) * LDA + k8 + tig]);
            a[mt][1] = __float_as_uint(As[(r + g + 8) * LDA + k8 + tig]);
            a[mt][2] = __float_as_uint(As[(r + g) * LDA + k8 + tig + 4]);
            a[mt][3] = __float_as_uint(As[(r + g + 8) * LDA + k8 + tig + 4]);
        }
        uint32_t b[4][2];
#pragma unroll
        for (int nt = 0; nt < 4; nt++) {
            int cc = wn + nt * 8 + g;
            b[nt][0] = __float_as_uint(Bs[cc * LDA + k8 + tig]);
            b[nt][1] = __float_as_uint(Bs[cc * LDA + k8 + tig + 4]);
        }
#pragma unroll
        for (int mt = 0; mt < 2; mt++)
#pragma unroll
            for (int nt = 0; nt < 4; nt++) {
                float* c = acc[mt][nt];
                asm volatile(
                    "mma.sync.aligned.m16n8k8.row.col.f32.tf32.tf32.f32 "
                    "{%0,%1,%2,%3},{%4,%5,%6,%7},{%8,%9},{%0,%1,%2,%3};\n"
                    : "+f"(c[0]), "+f"(c[1]), "+f"(c[2]), "+f"(c[3])
                    : "r"(a[mt][0]), "r"(a[mt][1]), "r"(a[mt][2]), "r"(a[mt][3]), "r"(b[nt][0]),
                      "r"(b[nt][1]));
            }
    }
}

__global__ void __launch_bounds__(256) xproj_kernel(const int* __restrict__ input,
                                                    const float* __restrict__ embed,
                                                    const float* __restrict__ w_ih,
                                                    const float* __restrict__ b_ih,
                                                    const float* __restrict__ b_hh) {
    float* smem = reinterpret_cast<float*>(dyn_smem);
    __shared__ int tok[128];

    const int tid = threadIdx.x;
    const int t = blockIdx.x;
    const int n0 = blockIdx.y * 64;

    if (tid < 128) tok[tid] = input[tid * TT + t];
    __syncthreads();

    const int wid = tid >> 5, lane = tid & 31;
    const int wm = (wid & 3) * 32, wn = (wid >> 2) * 32;
    const int g = lane >> 2, tig = lane & 3;

    auto load_tiles = [&](int kb, int s) {
        float* As = smem + s * XP_STAGE_FLOATS;
        float* Bs = As + 128 * LDA;
        int k0 = kb * 32;
#pragma unroll
        for (int i = 0; i < 4; i++) {
            int lin = tid + i * 256;
            int row = lin >> 3;
            int kk4 = (lin & 7) * 4;
            int k = k0 + kk4;
            int rem = EE - k;
            int bytes = rem >= 4 ? 16 : (rem > 0 ? rem * 4 : 0);
            const float* src = embed + (size_t)tok[row] * EE + (bytes ? k : 0);
            cp16z(smem_u32(&As[row * LDA + kk4]), src, bytes);
        }
#pragma unroll
        for (int i = 0; i < 2; i++) {
            int lin = tid + i * 256;
            int col = lin >> 3;
            int kk4 = (lin & 7) * 4;
            int k = k0 + kk4;
            int rem = EE - k;
            int bytes = rem >= 4 ? 16 : (rem > 0 ? rem * 4 : 0);
            const float* src = w_ih + (size_t)(n0 + col) * EE + (bytes ? k : 0);
            cp16z(smem_u32(&Bs[col * LDA + kk4]), src, bytes);
        }
        cp_commit();
    };

    float acc[2][4][4] = {};
    const int NKB = (EE + 31) / 32;  // 10
    load_tiles(0, 0);
    for (int kb = 0; kb < NKB; kb++) {
        if (kb + 1 < NKB) {
            load_tiles(kb + 1, (kb + 1) & 1);
            cp_wait<1>();
        } else {
            cp_wait<0>();
        }
        __syncthreads();
        const float* As = smem + (kb & 1) * XP_STAGE_FLOATS;
        compute_block_tf32(As, As + 128 * LDA, acc, wm, wn, g, tig);
        __syncthreads();
    }

    // epilogue -> g_gx2[t][cb][row][gate*16+hc], + biases
#pragma unroll
    for (int mt = 0; mt < 2; mt++) {
#pragma unroll
        for (int nt = 0; nt < 4; nt++) {
            int row0 = wm + mt * 16 + g;
            int col0 = wn + nt * 8 + 2 * tig;
            int j0 = n0 + col0;
            int gate = j0 >> 11;
            int q = j0 & 2047;
            int cb = q >> 4;
            int hc = q & 15;
            float bias0 = b_ih[j0] + b_hh[j0];
            float bias1 = b_ih[j0 + 1] + b_hh[j0 + 1];
            size_t base0 = (((size_t)t * 128 + cb) * 128 + row0) * 64 + gate * 16 + hc;
            g_gx2[base0] = acc[mt][nt][0] + bias0;
            g_gx2[base0 + 1] = acc[mt][nt][1] + bias1;
            size_t base2 = base0 + 8 * 64;
            g_gx2[base2] = acc[mt][nt][2] + bias0;
            g_gx2[base2 + 1] = acc[mt][nt][3] + bias1;
        }
    }
}

// ---------------- kernel 2: persistent fp16 LSTM, resident split-K ----------
// 256 CTAs (2/SM): blockIdx = half*128 + cb. CTA computes the 128x64 gate tile
// for cb over K half [half*1024, half*1024+1024). half 1 publishes its partial
// via global + release flag; half 0 combines, runs cell, publishes h. One
// global barrier (256 arrivals) per step.
#define KC 64
#define NCHUNK 16                              // 1024 / 64
#define AT_BYTES (128 * 128)                   // A tile: 16 KB
#define BT_BYTES (64 * 128)                    // B tile: 8 KB
#define STG_BYTES (AT_BYTES + BT_BYTES)        // 24576
#define NSTG 3
#define GX_OFF (NSTG * STG_BYTES)              // 73728
#define STEP_SMEM_BYTES (GX_OFF + 128 * 64 * 4)  // 106496 (2 CTAs/SM)
#define STEP_THREADS 256

__global__ void __launch_bounds__(STEP_THREADS, 2) step_persistent(float* __restrict__ d_out) {
    const uint32_t sbase = smem_u32(dyn_smem);
    const int tid = threadIdx.x;
    const int wid = tid >> 5, lane = tid & 31;
    const int cb = blockIdx.x & 127;
    const int half = blockIdx.x >> 7;
    const int h0 = cb * 16;
    const int kb0 = half * (HH / 2);
    const int wm = (wid & 3) * 32, wn = (wid >> 2) * 32;

    // per-lane ldmatrix coordinates
    const int arow = lane & 15;                        // A: row within 16-row tile
    const int acs = lane >> 4;                         // A: k-chunk select (0/1)
    const int brow = (lane & 7) + ((lane & 16) >> 1);  // B: row within 16-row group
    const int bcs = (lane >> 3) & 1;                   // B: k-chunk select
    const int g8 = lane >> 2, tig = lane & 3;

    for (int t = 0; t < TT; t++) {
        const __half* __restrict__ h_in = (t & 1) ? g_hb : g_ha;
        __half* __restrict__ h_out = (t & 1) ? g_ha : g_hb;

        auto issue_stage = [&](int c, int s) {
            uint32_t base = sbase + s * STG_BYTES;
            int k0 = kb0 + c * KC;
#pragma unroll
            for (int i = 0; i < 4; i++) {
                int lin = tid + i * STEP_THREADS;
                int row = lin >> 3;
                int o16 = lin & 7;
                uint32_t sw = SMEM_SWZ128(row * 128 + o16 * 16);
                cp16(base + sw, &h_in[row * HH + k0 + o16 * 8]);
            }
#pragma unroll
            for (int i = 0; i < 2; i++) {
                int lin = tid + i * STEP_THREADS;
                int n = lin >> 3;
                int o16 = lin & 7;
                int j = (n >> 4) * HH + h0 + (n & 15);
                uint32_t sw = SMEM_SWZ128(n * 128 + o16 * 16);
                cp16(base + BT_BYTES * 0 + AT_BYTES + sw, &g_w16[(size_t)j * HH + k0 + o16 * 8]);
            }
            cp_commit();
        };

        // gx prefetch (half 0 only; joins stage-0's commit group)
        if (half == 0) {
            const float* gx = &g_gx2[(((size_t)t * 128 + cb) * 128) * 64];
#pragma unroll
            for (int i = 0; i < 8; i++) {
                int lin = tid + i * STEP_THREADS;
                cp16(sbase + GX_OFF + lin * 16, gx + lin * 4);
            }
        }

        float acc[2][4][4] = {};

        issue_stage(0, 0);
        issue_stage(1, 1);

        for (int kb = 0; kb < NCHUNK; kb++) {
            cp_wait<1>();
            __syncthreads();
            int kn = kb + 2;
            if (kn < NCHUNK) issue_stage(kn, kn % NSTG);
            else cp_commit();  // keep group count exact in tail
            const uint32_t base = sbase + (kb % NSTG) * STG_BYTES;

            // register double-buffered fragments: load q+1 while mma q
            uint32_t a[2][2][4], b[2][2][4];
            auto load_frags = [&](int q, int pb) {
#pragma unroll
                for (int mt = 0; mt < 2; mt++) {
                    int row = wm + mt * 16 + arow;
                    uint32_t sw = SMEM_SWZ128(row * 128 + (2 * q + acs) * 16);
                    ldsm4(a[pb][mt], base + sw);
                }
#pragma unroll
                for (int nh = 0; nh < 2; nh++) {
                    int n = wn + nh * 16 + brow;
                    uint32_t sw = SMEM_SWZ128(n * 128 + (2 * q + bcs) * 16);
                    ldsm4(b[pb][nh], base + AT_BYTES + sw);
                }
            };
            load_frags(0, 0);
#pragma unroll
            for (int q = 0; q < 4; q++) {
                if (q < 3) load_frags(q + 1, (q + 1) & 1);
                const int pb = q & 1;
#pragma unroll
                for (int mt = 0; mt < 2; mt++)
#pragma unroll
                    for (int nt = 0; nt < 4; nt++)
                        mma_fp16(acc[mt][nt], a[pb][mt], b[pb][nt >> 1][(nt & 1) * 2],
                                 b[pb][nt >> 1][(nt & 1) * 2 + 1]);
            }
        }

        __syncthreads();

        if (half == 1) {
            // publish partial to global, release flag
            float* gp = g_part[cb];
#pragma unroll
            for (int mt = 0; mt < 2; mt++) {
#pragma unroll
                for (int nt = 0; nt < 4; nt++) {
                    int row0 = wm + mt * 16 + g8;
                    int col0 = wn + nt * 8 + 2 * tig;
                    gp[row0 * 64 + col0] = acc[mt][nt][0];
                    gp[row0 * 64 + col0 + 1] = acc[mt][nt][1];
                    gp[(row0 + 8) * 64 + col0] = acc[mt][nt][2];
                    gp[(row0 + 8) * 64 + col0 + 1] = acc[mt][nt][3];
                }
            }
            __syncthreads();
            __threadfence();
            if (tid == 0)
                asm volatile("st.release.gpu.global.u32 [%0], %1;" ::"l"(&g_pflag[cb]),
                             "r"((unsigned)(t + 1))
                             : "memory");
        } else {
            // stage own partial in smem: gsm[128][65] floats (stages 0-1 area)
            float* gsm = reinterpret_cast<float*>(dyn_smem);
#pragma unroll
            for (int mt = 0; mt < 2; mt++) {
#pragma unroll
                for (int nt = 0; nt < 4; nt++) {
                    int row0 = wm + mt * 16 + g8;
                    int col0 = wn + nt * 8 + 2 * tig;
                    gsm[row0 * 65 + col0] = acc[mt][nt][0];
                    gsm[row0 * 65 + col0 + 1] = acc[mt][nt][1];
                    gsm[(row0 + 8) * 65 + col0] = acc[mt][nt][2];
                    gsm[(row0 + 8) * 65 + col0 + 1] = acc[mt][nt][3];
                }
            }
            __syncthreads();
            if (tid == 0) {
                unsigned v;
                do {
                    asm volatile("ld.acquire.gpu.global.u32 %0, [%1];" : "=r"(v)
                                 : "l"(&g_pflag[cb]));
                    if (v < (unsigned)(t + 1)) __nanosleep(32);
                } while (v < (unsigned)(t + 1));
            }
            __syncthreads();

            // LSTM cell: own partial (smem) + other partial (global) + gx (smem)
            const float* __restrict__ gxs = reinterpret_cast<const float*>(dyn_smem + GX_OFF);
            const float* __restrict__ gp = g_part[cb];
            const int b = tid >> 1;
            const int hh = (tid & 1) * 8;
            float* __restrict__ cc = &g_c2[(cb * 128 + b) * 16];
#pragma unroll
            for (int i = 0; i < 8; i++) {
                int hc = hh + i;
                int c0 = 0 * 16 + hc, c1 = 1 * 16 + hc, c2 = 2 * 16 + hc, c3 = 3 * 16 + hc;
                float xi = gsm[b * 65 + c0] + gp[b * 64 + c0] + gxs[b * 64 + c0];
                float xf = gsm[b * 65 + c1] + gp[b * 64 + c1] + gxs[b * 64 + c1];
                float xg = gsm[b * 65 + c2] + gp[b * 64 + c2] + gxs[b * 64 + c2];
                float xo = gsm[b * 65 + c3] + gp[b * 64 + c3] + gxs[b * 64 + c3];
                float ig = sigmoidf_(xi);
                float fg = sigmoidf_(xf);
                float gg = tanhf(xg);
                float og = sigmoidf_(xo);
                float cn = fg * cc[hc] + ig * gg;
                cc[hc] = cn;
                float hv = og * tanhf(cn);
                h_out[b * HH + h0 + hc] = __float2half(hv);
                if (t == TT - 1) d_out[b * HH + h0 + hc] = hv;
            }
        }

        // ---- global barrier (all 256 CTAs) ----
        if (t < TT - 1) {
            __syncthreads();
            __threadfence();
            if (tid == 0) {
                atomicAdd(&g_bar, 1u);
                const unsigned target = 256u * (unsigned)(t + 1);
                unsigned v;
                do {
                    asm volatile("ld.acquire.gpu.global.u32 %0, [%1];" : "=r"(v) : "l"(&g_bar));
                    if (v < target) __nanosleep(64);
                } while (v < target);
            }
            __syncthreads();
        }
    }
}

// ---------------- launch ----------------------------------------------------
extern "C" void kernel_launch(void* const* d_in, const int* in_sizes, int n_in, void* d_out,
                              int out_size) {
    const int* input = (const int*)d_in[0];
    const float* embed = (const float*)d_in[1];
    const float* w_ih = (const float*)d_in[2];
    const float* w_hh = (const float*)d_in[3];
    const float* b_ih = (const float*)d_in[4];
    const float* b_hh = (const float*)d_in[5];
    float* out = (float*)d_out;

    cudaFuncSetAttribute(xproj_kernel, cudaFuncAttributeMaxDynamicSharedMemorySize, XP_SMEM_BYTES);
    cudaFuncSetAttribute(step_persistent, cudaFuncAttributeMaxDynamicSharedMemorySize,
                         STEP_SMEM_BYTES);

    zero_kernel<<<(BB * HH + 255) / 256, 256>>>();
    wconv_kernel<<<(int)(((size_t)G4 * HH / 4 + 255) / 256), 256>>>(w_hh);
    xproj_kernel<<<dim3(TT, 128), 256, XP_SMEM_BYTES>>>(input, embed, w_ih, b_ih, b_hh);
    step_persistent<<<256, STEP_THREADS, STEP_SMEM_BYTES>>>(out);
}

// round 12
// speedup vs baseline: 1.5077x; 1.5077x over previous
#include <cuda_runtime.h>
#include <cuda_fp16.h>
#include <cstdint>

#define BB 128          // batch
#define TT 64           // time steps
#define EE 300          // embed dim
#define HH 2048         // hidden
#define G4 8192         // 4*H

// ---------------- scratch (device globals; no allocation allowed) ----------
__device__ float g_gx2[(size_t)TT * 128 * 128 * 64];   // [t][cb][b][gate*16+hc]
__device__ __half g_w16[(size_t)G4 * HH];              // W_hh fp16
__device__ __half g_ha[BB * HH];                       // hidden state ping
__device__ __half g_hb[BB * HH];                       // hidden state pong
__device__ float g_c2[BB * HH];                        // cell state [cb][b][16]
__device__ unsigned g_bar;                             // persistent-kernel barrier

// single dynamic smem symbol shared by all kernels
extern __shared__ __align__(1024) char dyn_smem[];

// ---------------- helpers --------------------------------------------------
__device__ __forceinline__ uint32_t smem_u32(const void* p) {
    return (uint32_t)__cvta_generic_to_shared(p);
}
__device__ __forceinline__ void cp16(uint32_t dst, const void* src) {
    asm volatile("cp.async.cg.shared.global [%0], [%1], 16;\n" ::"r"(dst), "l"(src));
}
__device__ __forceinline__ void cp16z(uint32_t dst, const void* src, int bytes) {
    asm volatile("cp.async.ca.shared.global [%0], [%1], 16, %2;\n" ::"r"(dst), "l"(src), "r"(bytes));
}
__device__ __forceinline__ void cp_commit() { asm volatile("cp.async.commit_group;\n"); }
template <int N> __device__ __forceinline__ void cp_wait() {
    asm volatile("cp.async.wait_group %0;\n" ::"n"(N));
}
__device__ __forceinline__ void mma_fp16(float c[4], const uint32_t a[4], uint32_t b0,
                                         uint32_t b1) {
    asm volatile(
        "mma.sync.aligned.m16n8k16.row.col.f32.f16.f16.f32 "
        "{%0,%1,%2,%3},{%4,%5,%6,%7},{%8,%9},{%0,%1,%2,%3};\n"
        : "+f"(c[0]), "+f"(c[1]), "+f"(c[2]), "+f"(c[3])
        : "r"(a[0]), "r"(a[1]), "r"(a[2]), "r"(a[3]), "r"(b0), "r"(b1));
}
__device__ __forceinline__ void ldsm4(uint32_t r[4], uint32_t addr) {
    asm volatile("ldmatrix.sync.aligned.m8n8.x4.shared.b16 {%0,%1,%2,%3}, [%4];"
                 : "=r"(r[0]), "=r"(r[1]), "=r"(r[2]), "=r"(r[3])
                 : "r"(addr));
}
__device__ __forceinline__ float sigmoidf_(float x) { return 1.0f / (1.0f + __expf(-x)); }

#define SMEM_SWZ128(x) ((x) ^ (((x) >> 3) & 0x70))

// ---------------- init / W convert ------------------------------------------
__global__ void zero_kernel() {
    int i = blockIdx.x * blockDim.x + threadIdx.x;
    if (i < BB * HH) {
        g_ha[i] = __float2half(0.f);
        g_c2[i] = 0.f;
    }
    if (i == 0) g_bar = 0u;
}

__global__ void wconv_kernel(const float* __restrict__ w) {
    size_t i = ((size_t)blockIdx.x * blockDim.x + threadIdx.x) * 4;
    if (i < (size_t)G4 * HH) {
        float4 v = *reinterpret_cast<const float4*>(w + i);
        g_w16[i] = __float2half(v.x);
        g_w16[i + 1] = __float2half(v.y);
        g_w16[i + 2] = __float2half(v.z);
        g_w16[i + 3] = __float2half(v.w);
    }
}

// ---------------- kernel 1: embedding gather + input projection (tf32 SIMT) -
#define LDA 36
#define XP_STAGE_FLOATS ((128 + 64) * LDA)
#define XP_SMEM_BYTES (2 * XP_STAGE_FLOATS * 4)

__device__ __forceinline__ void compute_block_tf32(const float* __restrict__ As,
                                                   const float* __restrict__ Bs,
                                                   float acc[2][4][4], int wm, int wn, int g,
                                                   int tig) {
#pragma unroll
    for (int k8 = 0; k8 < 32; k8 += 8) {
        uint32_t a[2][4];
#pragma unroll
        for (int mt = 0; mt < 2; mt++) {
            int r = wm + mt * 16;
            a[mt][0] = __float_as_uint(As[(r + g) * LDA + k8 + tig]);
            a[mt][1] = __float_as_uint(As[(r + g + 8) * LDA + k8 + tig]);
            a[mt][2] = __float_as_uint(As[(r + g) * LDA + k8 + tig + 4]);
            a[mt][3] = __float_as_uint(As[(r + g + 8) * LDA + k8 + tig + 4]);
        }
        uint32_t b[4][2];
#pragma unroll
        for (int nt = 0; nt < 4; nt++) {
            int cc = wn + nt * 8 + g;
            b[nt][0] = __float_as_uint(Bs[cc * LDA + k8 + tig]);
            b[nt][1] = __float_as_uint(Bs[cc * LDA + k8 + tig + 4]);
        }
#pragma unroll
        for (int mt = 0; mt < 2; mt++)
#pragma unroll
            for (int nt = 0; nt < 4; nt++) {
                float* c = acc[mt][nt];
                asm volatile(
                    "mma.sync.aligned.m16n8k8.row.col.f32.tf32.tf32.f32 "
                    "{%0,%1,%2,%3},{%4,%5,%6,%7},{%8,%9},{%0,%1,%2,%3};\n"
                    : "+f"(c[0]), "+f"(c[1]), "+f"(c[2]), "+f"(c[3])
                    : "r"(a[mt][0]), "r"(a[mt][1]), "r"(a[mt][2]), "r"(a[mt][3]), "r"(b[nt][0]),
                      "r"(b[nt][1]));
            }
    }
}

__global__ void __launch_bounds__(256) xproj_kernel(const int* __restrict__ input,
                                                    const float* __restrict__ embed,
                                                    const float* __restrict__ w_ih,
                                                    const float* __restrict__ b_ih,
                                                    const float* __restrict__ b_hh) {
    float* smem = reinterpret_cast<float*>(dyn_smem);
    __shared__ int tok[128];

    const int tid = threadIdx.x;
    const int t = blockIdx.x;
    const int n0 = blockIdx.y * 64;

    if (tid < 128) tok[tid] = input[tid * TT + t];
    __syncthreads();

    const int wid = tid >> 5, lane = tid & 31;
    const int wm = (wid & 3) * 32, wn = (wid >> 2) * 32;
    const int g = lane >> 2, tig = lane & 3;

    auto load_tiles = [&](int kb, int s) {
        float* As = smem + s * XP_STAGE_FLOATS;
        float* Bs = As + 128 * LDA;
        int k0 = kb * 32;
#pragma unroll
        for (int i = 0; i < 4; i++) {
            int lin = tid + i * 256;
            int row = lin >> 3;
            int kk4 = (lin & 7) * 4;
            int k = k0 + kk4;
            int rem = EE - k;
            int bytes = rem >= 4 ? 16 : (rem > 0 ? rem * 4 : 0);
            const float* src = embed + (size_t)tok[row] * EE + (bytes ? k : 0);
            cp16z(smem_u32(&As[row * LDA + kk4]), src, bytes);
        }
#pragma unroll
        for (int i = 0; i < 2; i++) {
            int lin = tid + i * 256;
            int col = lin >> 3;
            int kk4 = (lin & 7) * 4;
            int k = k0 + kk4;
            int rem = EE - k;
            int bytes = rem >= 4 ? 16 : (rem > 0 ? rem * 4 : 0);
            const float* src = w_ih + (size_t)(n0 + col) * EE + (bytes ? k : 0);
            cp16z(smem_u32(&Bs[col * LDA + kk4]), src, bytes);
        }
        cp_commit();
    };

    float acc[2][4][4] = {};
    const int NKB = (EE + 31) / 32;  // 10
    load_tiles(0, 0);
    for (int kb = 0; kb < NKB; kb++) {
        if (kb + 1 < NKB) {
            load_tiles(kb + 1, (kb + 1) & 1);
            cp_wait<1>();
        } else {
            cp_wait<0>();
        }
        __syncthreads();
        const float* As = smem + (kb & 1) * XP_STAGE_FLOATS;
        compute_block_tf32(As, As + 128 * LDA, acc, wm, wn, g, tig);
        __syncthreads();
    }

    // epilogue -> g_gx2[t][cb][row][gate*16+hc], + biases
#pragma unroll
    for (int mt = 0; mt < 2; mt++) {
#pragma unroll
        for (int nt = 0; nt < 4; nt++) {
            int row0 = wm + mt * 16 + g;
            int col0 = wn + nt * 8 + 2 * tig;
            int j0 = n0 + col0;
            int gate = j0 >> 11;
            int q = j0 & 2047;
            int cb = q >> 4;
            int hc = q & 15;
            float bias0 = b_ih[j0] + b_hh[j0];
            float bias1 = b_ih[j0 + 1] + b_hh[j0 + 1];
            size_t base0 = (((size_t)t * 128 + cb) * 128 + row0) * 64 + gate * 16 + hc;
            g_gx2[base0] = acc[mt][nt][0] + bias0;
            g_gx2[base0 + 1] = acc[mt][nt][1] + bias1;
            size_t base2 = base0 + 8 * 64;
            g_gx2[base2] = acc[mt][nt][2] + bias0;
            g_gx2[base2 + 1] = acc[mt][nt][3] + bias1;
        }
    }
}

// ---------------- kernel 2: persistent fp16 LSTM (all 64 steps) -------------
// 128 resident CTAs; CTA cb computes D[128 batch, 64 cols], col = gate*16+hc.
// KC=128 chunks; NSTG=3. W + gx for the next step are prefetched BEFORE the
// inter-step barrier (they don't depend on h); only the h-halves of stages 0/1
// load after it. gsm (gate staging) lives in its own smem region.
#define KC 128
#define NCHUNK (HH / KC)                       // 16
#define ASUB_BYTES (128 * 128)                 // A sub-tile 16 KB
#define BSUB_BYTES (64 * 128)                  // B sub-tile 8 KB
#define A_BYTES (2 * ASUB_BYTES)               // 32 KB per stage
#define STG_BYTES (A_BYTES + 2 * BSUB_BYTES)   // 49152
#define NSTG 3
#define GX_OFF (NSTG * STG_BYTES)              // 147456
#define GSM_OFF (GX_OFF + 128 * 64 * 4)        // 180224
#define STEP_SMEM_BYTES (GSM_OFF + 128 * 65 * 4)  // 213504
#define STEP_THREADS 256

__global__ void __launch_bounds__(STEP_THREADS) step_persistent(float* __restrict__ d_out) {
    const uint32_t sbase = smem_u32(dyn_smem);
    const int tid = threadIdx.x;
    const int wid = tid >> 5, lane = tid & 31;
    const int cb = blockIdx.x;
    const int h0 = cb * 16;
    const int wm = (wid & 3) * 32, wn = (wid >> 2) * 32;

    // per-lane ldmatrix coordinates
    const int arow = lane & 15;                        // A: row within 16-row tile
    const int acs = lane >> 4;                         // A: k-chunk select (0/1)
    const int brow = (lane & 7) + ((lane & 16) >> 1);  // B: row within 16-row group
    const int bcs = (lane >> 3) & 1;                   // B: k-chunk select
    const int g8 = lane >> 2, tig = lane & 3;

    // W-half of a stage (both 64-k sub-tiles); no commit
    auto issue_w = [&](int c, int s) {
        uint32_t bb0 = sbase + s * STG_BYTES + A_BYTES;
#pragma unroll
        for (int s2 = 0; s2 < 2; s2++) {
            int k0 = c * KC + s2 * 64;
            uint32_t bbase = bb0 + s2 * BSUB_BYTES;
#pragma unroll
            for (int i = 0; i < 2; i++) {
                int lin = tid + i * STEP_THREADS;
                int n = lin >> 3;
                int o16 = lin & 7;
                int j = (n >> 4) * HH + h0 + (n & 15);
                uint32_t sw = SMEM_SWZ128(n * 128 + o16 * 16);
                cp16(bbase + sw, &g_w16[(size_t)j * HH + k0 + o16 * 8]);
            }
        }
    };
    // h-half of a stage; no commit
    auto issue_h = [&](const __half* h_in, int c, int s) {
        uint32_t ab0 = sbase + s * STG_BYTES;
#pragma unroll
        for (int s2 = 0; s2 < 2; s2++) {
            int k0 = c * KC + s2 * 64;
            uint32_t abase = ab0 + s2 * ASUB_BYTES;
#pragma unroll
            for (int i = 0; i < 4; i++) {
                int lin = tid + i * STEP_THREADS;
                int row = lin >> 3;
                int o16 = lin & 7;
                uint32_t sw = SMEM_SWZ128(row * 128 + o16 * 16);
                cp16(abase + sw, &h_in[row * HH + k0 + o16 * 8]);
            }
        }
    };
    auto issue_gx = [&](int t) {
        const float* gx = &g_gx2[(((size_t)t * 128 + cb) * 128) * 64];
#pragma unroll
        for (int i = 0; i < 8; i++) {
            int lin = tid + i * STEP_THREADS;
            cp16(sbase + GX_OFF + lin * 16, gx + lin * 4);
        }
    };

    // t=0 prologue: same group order as the per-step epilogue produces
    issue_w(0, 0);
    issue_gx(0);
    cp_commit();
    issue_w(1, 1);
    cp_commit();
    issue_h(g_ha, 0, 0);
    cp_commit();
    issue_h(g_ha, 1, 1);
    cp_commit();

    for (int t = 0; t < TT; t++) {
        const __half* __restrict__ h_in = (t & 1) ? g_hb : g_ha;
        __half* __restrict__ h_out = (t & 1) ? g_ha : g_hb;

        float acc[2][4][4] = {};

        for (int kb = 0; kb < NCHUNK; kb++) {
            cp_wait<1>();
            __syncthreads();
            int kn = kb + 2;
            if (kn < NCHUNK) {
                issue_h(h_in, kn, kn % NSTG);
                issue_w(kn, kn % NSTG);
            }
            cp_commit();  // one commit per iteration keeps the group count exact
            const uint32_t base = sbase + (kb % NSTG) * STG_BYTES;

            // register double-buffered fragments: load q+1 while mma q
            uint32_t a[2][2][4], b[2][2][4];
            auto load_frags = [&](int q, int pb) {
                const int ks = q >> 2, qq = q & 3;
                const uint32_t ab = base + ks * ASUB_BYTES;
                const uint32_t bb = base + A_BYTES + ks * BSUB_BYTES;
#pragma unroll
                for (int mt = 0; mt < 2; mt++) {
                    int row = wm + mt * 16 + arow;
                    uint32_t sw = SMEM_SWZ128(row * 128 + (2 * qq + acs) * 16);
                    ldsm4(a[pb][mt], ab + sw);
                }
#pragma unroll
                for (int nh = 0; nh < 2; nh++) {
                    int n = wn + nh * 16 + brow;
                    uint32_t sw = SMEM_SWZ128(n * 128 + (2 * qq + bcs) * 16);
                    ldsm4(b[pb][nh], bb + sw);
                }
            };
            load_frags(0, 0);
#pragma unroll
            for (int q = 0; q < 8; q++) {
                if (q < 7) load_frags(q + 1, (q + 1) & 1);
                const int pb = q & 1;
#pragma unroll
                for (int mt = 0; mt < 2; mt++)
#pragma unroll
                    for (int nt = 0; nt < 4; nt++)
                        mma_fp16(acc[mt][nt], a[pb][mt], b[pb][nt >> 1][(nt & 1) * 2],
                                 b[pb][nt >> 1][(nt & 1) * 2 + 1]);
            }
        }

        // stage gates in dedicated gsm region (no conflict with stage buffers)
        float* gsm = reinterpret_cast<float*>(dyn_smem + GSM_OFF);
#pragma unroll
        for (int mt = 0; mt < 2; mt++) {
#pragma unroll
            for (int nt = 0; nt < 4; nt++) {
                int row0 = wm + mt * 16 + g8;
                int col0 = wn + nt * 8 + 2 * tig;
                gsm[row0 * 65 + col0] = acc[mt][nt][0];
                gsm[row0 * 65 + col0 + 1] = acc[mt][nt][1];
                gsm[(row0 + 8) * 65 + col0] = acc[mt][nt][2];
                gsm[(row0 + 8) * 65 + col0 + 1] = acc[mt][nt][3];
            }
        }
        __syncthreads();  // gsm visible to all; all compute done (stages free)

        // LSTM cell: 128 b x 16 h, 8 per thread; vectorized global traffic
        {
            const float* __restrict__ gxs = reinterpret_cast<const float*>(dyn_smem + GX_OFF);
            const int b = tid >> 1;
            const int hh = (tid & 1) * 8;
            float* __restrict__ cc = &g_c2[(cb * 128 + b) * 16 + hh];
            float4 cA = *reinterpret_cast<float4*>(cc);
            float4 cB = *reinterpret_cast<float4*>(cc + 4);
            float cv[8] = {cA.x, cA.y, cA.z, cA.w, cB.x, cB.y, cB.z, cB.w};
            __align__(16) __half hv8[8];
            float hvf[8];
#pragma unroll
            for (int i = 0; i < 8; i++) {
                int hc = hh + i;
                float xi = gsm[b * 65 + 0 * 16 + hc] + gxs[b * 64 + 0 * 16 + hc];
                float xf = gsm[b * 65 + 1 * 16 + hc] + gxs[b * 64 + 1 * 16 + hc];
                float xg = gsm[b * 65 + 2 * 16 + hc] + gxs[b * 64 + 2 * 16 + hc];
                float xo = gsm[b * 65 + 3 * 16 + hc] + gxs[b * 64 + 3 * 16 + hc];
                float ig = sigmoidf_(xi);
                float fg = sigmoidf_(xf);
                float gg = tanhf(xg);
                float og = sigmoidf_(xo);
                float cn = fg * cv[i] + ig * gg;
                cv[i] = cn;
                float hv = og * tanhf(cn);
                hvf[i] = hv;
                hv8[i] = __float2half(hv);
            }
            *reinterpret_cast<float4*>(cc) = make_float4(cv[0], cv[1], cv[2], cv[3]);
            *reinterpret_cast<float4*>(cc + 4) = make_float4(cv[4], cv[5], cv[6], cv[7]);
            *reinterpret_cast<uint4*>(&h_out[b * HH + h0 + hh]) =
                *reinterpret_cast<uint4*>(hv8);
            if (t == TT - 1) {
                *reinterpret_cast<float4*>(&d_out[b * HH + h0 + hh]) =
                    make_float4(hvf[0], hvf[1], hvf[2], hvf[3]);
                *reinterpret_cast<float4*>(&d_out[b * HH + h0 + hh + 4]) =
                    make_float4(hvf[4], hvf[5], hvf[6], hvf[7]);
            }
        }

        if (t < TT - 1) {
            __syncthreads();  // all gx reads done before refilling GX region
            // pre-barrier: W + gx for step t+1 (independent of new h)
            issue_w(0, 0);
            issue_gx(t + 1);
            cp_commit();
            issue_w(1, 1);
            cp_commit();
            // global barrier (128 CTAs)
            __threadfence();
            if (tid == 0) {
                atomicAdd(&g_bar, 1u);
                const unsigned target = 128u * (unsigned)(t + 1);
                unsigned v;
                do {
                    asm volatile("ld.acquire.gpu.global.u32 %0, [%1];" : "=r"(v) : "l"(&g_bar));
                    if (v < target) __nanosleep(64);
                } while (v < target);
            }
            __syncthreads();
            // post-barrier: h halves of stages 0/1 (h_out just published by all CTAs)
            issue_h(h_out, 0, 0);
            cp_commit();
            issue_h(h_out, 1, 1);
            cp_commit();
        }
    }
}

// ---------------- launch ----------------------------------------------------
extern "C" void kernel_launch(void* const* d_in, const int* in_sizes, int n_in, void* d_out,
                              int out_size) {
    const int* input = (const int*)d_in[0];
    const float* embed = (const float*)d_in[1];
    const float* w_ih = (const float*)d_in[2];
    const float* w_hh = (const float*)d_in[3];
    const float* b_ih = (const float*)d_in[4];
    const float* b_hh = (const float*)d_in[5];
    float* out = (float*)d_out;

    cudaFuncSetAttribute(xproj_kernel, cudaFuncAttributeMaxDynamicSharedMemorySize, XP_SMEM_BYTES);
    cudaFuncSetAttribute(step_persistent, cudaFuncAttributeMaxDynamicSharedMemorySize,
                         STEP_SMEM_BYTES);

    zero_kernel<<<(BB * HH + 255) / 256, 256>>>();
    wconv_kernel<<<(int)(((size_t)G4 * HH / 4 + 255) / 256), 256>>>(w_hh);
    xproj_kernel<<<dim3(TT, 128), 256, XP_SMEM_BYTES>>>(input, embed, w_ih, b_ih, b_hh);
    step_persistent<<<128, STEP_THREADS, STEP_SMEM_BYTES>>>(out);
}

// round 13
// speedup vs baseline: 1.7243x; 1.1437x over previous
#include <cuda_runtime.h>
#include <cuda_fp16.h>
#include <cstdint>

#define BB 128          // batch
#define TT 64           // time steps
#define EE 300          // embed dim
#define EP 320          // padded embed dim (5 x 64)
#define HH 2048         // hidden
#define G4 8192         // 4*H

// ---------------- scratch (device globals; no allocation allowed) ----------
__device__ float g_gx2[(size_t)TT * 128 * 128 * 64];   // [t][cb][b][gate*16+hc]
__device__ __half g_w16[(size_t)G4 * HH];              // W_hh fp16
__device__ __half g_x16[(size_t)TT * BB * EP];         // gathered embeddings fp16 (padded)
__device__ __half g_wih16[(size_t)G4 * EP];            // W_ih fp16 (padded)
__device__ __half g_ha[BB * HH];                       // hidden state ping
__device__ __half g_hb[BB * HH];                       // hidden state pong
__device__ float g_c2[BB * HH];                        // cell state [cb][b][16]
__device__ unsigned g_bar;                             // persistent-kernel barrier

// single dynamic smem symbol shared by all kernels
extern __shared__ __align__(1024) char dyn_smem[];

// ---------------- helpers --------------------------------------------------
__device__ __forceinline__ uint32_t smem_u32(const void* p) {
    return (uint32_t)__cvta_generic_to_shared(p);
}
__device__ __forceinline__ void cp16(uint32_t dst, const void* src) {
    asm volatile("cp.async.cg.shared.global [%0], [%1], 16;\n" ::"r"(dst), "l"(src));
}
__device__ __forceinline__ void cp_commit() { asm volatile("cp.async.commit_group;\n"); }
template <int N> __device__ __forceinline__ void cp_wait() {
    asm volatile("cp.async.wait_group %0;\n" ::"n"(N));
}
__device__ __forceinline__ void mma_fp16(float c[4], const uint32_t a[4], uint32_t b0,
                                         uint32_t b1) {
    asm volatile(
        "mma.sync.aligned.m16n8k16.row.col.f32.f16.f16.f32 "
        "{%0,%1,%2,%3},{%4,%5,%6,%7},{%8,%9},{%0,%1,%2,%3};\n"
        : "+f"(c[0]), "+f"(c[1]), "+f"(c[2]), "+f"(c[3])
        : "r"(a[0]), "r"(a[1]), "r"(a[2]), "r"(a[3]), "r"(b0), "r"(b1));
}
__device__ __forceinline__ void ldsm4(uint32_t r[4], uint32_t addr) {
    asm volatile("ldmatrix.sync.aligned.m8n8.x4.shared.b16 {%0,%1,%2,%3}, [%4];"
                 : "=r"(r[0]), "=r"(r[1]), "=r"(r[2]), "=r"(r[3])
                 : "r"(addr));
}
__device__ __forceinline__ float sigmoidf_(float x) { return 1.0f / (1.0f + __expf(-x)); }

#define SMEM_SWZ128(x) ((x) ^ (((x) >> 3) & 0x70))

// ---------------- init / converters -----------------------------------------
__global__ void zero_kernel() {
    int i = blockIdx.x * blockDim.x + threadIdx.x;
    if (i < BB * HH) {
        g_ha[i] = __float2half(0.f);
        g_c2[i] = 0.f;
    }
    if (i == 0) g_bar = 0u;
}

__global__ void wconv_kernel(const float* __restrict__ w) {
    size_t i = ((size_t)blockIdx.x * blockDim.x + threadIdx.x) * 4;
    if (i < (size_t)G4 * HH) {
        float4 v = *reinterpret_cast<const float4*>(w + i);
        g_w16[i] = __float2half(v.x);
        g_w16[i + 1] = __float2half(v.y);
        g_w16[i + 2] = __float2half(v.z);
        g_w16[i + 3] = __float2half(v.w);
    }
}

// gather embeddings + convert w_ih to fp16 (rows padded 300 -> 320 with zeros)
__global__ void __launch_bounds__(256) gather16_kernel(const int* __restrict__ input,
                                                       const float* __restrict__ embed,
                                                       const float* __restrict__ w_ih) {
    const int wid = threadIdx.x >> 5, lane = threadIdx.x & 31;
    const int row = blockIdx.x * 8 + wid;  // 0..8191
    if (blockIdx.y == 0) {
        // x16 row: (t, b) with row = t*128 + b
        const int t = row >> 7, b = row & 127;
        const int tok = input[b * TT + t];
        const float* __restrict__ src = embed + (size_t)tok * EE;
        __half* __restrict__ dst = g_x16 + (size_t)row * EP;
        for (int c = lane; c < EP; c += 32)
            dst[c] = (c < EE) ? __float2half(src[c]) : __float2half(0.f);
    } else {
        const float* __restrict__ src = w_ih + (size_t)row * EE;
        __half* __restrict__ dst = g_wih16 + (size_t)row * EP;
        for (int c = lane; c < EP; c += 32)
            dst[c] = (c < EE) ? __float2half(src[c]) : __float2half(0.f);
    }
}

// ---------------- kernel 1: input projection, fp16 tensor path --------------
// grid (32, 64): BM=256 rows (= 2 t x 128 b), BN=128 cols. 8 warps (4M x 2N),
// warp tile 64x64. K = 320 in 5 chunks of 64.
#define XQ_KC 64
#define XQ_NCH (EP / XQ_KC)                    // 5
#define XQ_AT (256 * 128)                      // A tile 32 KB
#define XQ_BT (128 * 128)                      // B tile 16 KB
#define XQ_STG (XQ_AT + XQ_BT)                 // 49152
#define XQ_NSTG 3
#define XQ_SMEM (XQ_NSTG * XQ_STG)             // 147456

__global__ void __launch_bounds__(256) xproj16_kernel(const float* __restrict__ b_ih,
                                                      const float* __restrict__ b_hh) {
    const uint32_t sbase = smem_u32(dyn_smem);
    const int tid = threadIdx.x;
    const int wid = tid >> 5, lane = tid & 31;
    const int m0 = blockIdx.x * 256;
    const int n0 = blockIdx.y * 128;
    const int wm = (wid & 3) * 64, wn = (wid >> 2) * 64;

    const int arow = lane & 15;
    const int acs = lane >> 4;
    const int brow = (lane & 7) + ((lane & 16) >> 1);
    const int bcs = (lane >> 3) & 1;
    const int g8 = lane >> 2, tig = lane & 3;

    auto issue_stage = [&](int c, int s) {
        uint32_t base = sbase + s * XQ_STG;
        int k0 = c * XQ_KC;
#pragma unroll
        for (int i = 0; i < 8; i++) {
            int lin = tid + i * 256;
            int row = lin >> 3;
            int o16 = lin & 7;
            uint32_t sw = SMEM_SWZ128(row * 128 + o16 * 16);
            cp16(base + sw, &g_x16[(size_t)(m0 + row) * EP + k0 + o16 * 8]);
        }
#pragma unroll
        for (int i = 0; i < 4; i++) {
            int lin = tid + i * 256;
            int n = lin >> 3;
            int o16 = lin & 7;
            uint32_t sw = SMEM_SWZ128(n * 128 + o16 * 16);
            cp16(base + XQ_AT + sw, &g_wih16[(size_t)(n0 + n) * EP + k0 + o16 * 8]);
        }
        cp_commit();
    };

    float acc[4][8][4] = {};

    issue_stage(0, 0);
    issue_stage(1, 1);

    for (int kb = 0; kb < XQ_NCH; kb++) {
        cp_wait<1>();
        __syncthreads();
        int kn = kb + 2;
        if (kn < XQ_NCH) issue_stage(kn, kn % XQ_NSTG);
        else cp_commit();
        const uint32_t base = sbase + (kb % XQ_NSTG) * XQ_STG;

#pragma unroll
        for (int q = 0; q < 4; q++) {
            uint32_t a[4][4], b[4][4];
#pragma unroll
            for (int mt = 0; mt < 4; mt++) {
                int row = wm + mt * 16 + arow;
                uint32_t sw = SMEM_SWZ128(row * 128 + (2 * q + acs) * 16);
                ldsm4(a[mt], base + sw);
            }
#pragma unroll
            for (int nh = 0; nh < 4; nh++) {
                int n = wn + nh * 16 + brow;
                uint32_t sw = SMEM_SWZ128(n * 128 + (2 * q + bcs) * 16);
                ldsm4(b[nh], base + XQ_AT + sw);
            }
#pragma unroll
            for (int mt = 0; mt < 4; mt++)
#pragma unroll
                for (int nt = 0; nt < 8; nt++)
                    mma_fp16(acc[mt][nt], a[mt], b[nt >> 1][(nt & 1) * 2],
                             b[nt >> 1][(nt & 1) * 2 + 1]);
        }
    }

    // epilogue: add biases, write g_gx2[t][cb][b][gate*16+hc]
#pragma unroll
    for (int mt = 0; mt < 4; mt++) {
#pragma unroll
        for (int nt = 0; nt < 8; nt++) {
            int row0 = wm + mt * 16 + g8;
            int col0 = wn + nt * 8 + 2 * tig;
            int rg = m0 + row0;
            int t = rg >> 7, b = rg & 127;
            int j0 = n0 + col0;
            int gate = j0 >> 11;
            int qq = j0 & 2047;
            int cb = qq >> 4;
            int hc = qq & 15;
            float bias0 = b_ih[j0] + b_hh[j0];
            float bias1 = b_ih[j0 + 1] + b_hh[j0 + 1];
            size_t base0 = (((size_t)t * 128 + cb) * 128 + b) * 64 + gate * 16 + hc;
            g_gx2[base0] = acc[mt][nt][0] + bias0;
            g_gx2[base0 + 1] = acc[mt][nt][1] + bias1;
            size_t base2 = base0 + 8 * 64;
            g_gx2[base2] = acc[mt][nt][2] + bias0;
            g_gx2[base2 + 1] = acc[mt][nt][3] + bias1;
        }
    }
}

// ---------------- kernel 2: persistent fp16 LSTM (all 64 steps) -------------
// (unchanged champion from round 12)
#define KC 128
#define NCHUNK (HH / KC)                       // 16
#define ASUB_BYTES (128 * 128)                 // A sub-tile 16 KB
#define BSUB_BYTES (64 * 128)                  // B sub-tile 8 KB
#define A_BYTES (2 * ASUB_BYTES)               // 32 KB per stage
#define STG_BYTES (A_BYTES + 2 * BSUB_BYTES)   // 49152
#define NSTG 3
#define GX_OFF (NSTG * STG_BYTES)              // 147456
#define GSM_OFF (GX_OFF + 128 * 64 * 4)        // 180224
#define STEP_SMEM_BYTES (GSM_OFF + 128 * 65 * 4)  // 213504
#define STEP_THREADS 256

__global__ void __launch_bounds__(STEP_THREADS) step_persistent(float* __restrict__ d_out) {
    const uint32_t sbase = smem_u32(dyn_smem);
    const int tid = threadIdx.x;
    const int wid = tid >> 5, lane = tid & 31;
    const int cb = blockIdx.x;
    const int h0 = cb * 16;
    const int wm = (wid & 3) * 32, wn = (wid >> 2) * 32;

    const int arow = lane & 15;
    const int acs = lane >> 4;
    const int brow = (lane & 7) + ((lane & 16) >> 1);
    const int bcs = (lane >> 3) & 1;
    const int g8 = lane >> 2, tig = lane & 3;

    auto issue_w = [&](int c, int s) {
        uint32_t bb0 = sbase + s * STG_BYTES + A_BYTES;
#pragma unroll
        for (int s2 = 0; s2 < 2; s2++) {
            int k0 = c * KC + s2 * 64;
            uint32_t bbase = bb0 + s2 * BSUB_BYTES;
#pragma unroll
            for (int i = 0; i < 2; i++) {
                int lin = tid + i * STEP_THREADS;
                int n = lin >> 3;
                int o16 = lin & 7;
                int j = (n >> 4) * HH + h0 + (n & 15);
                uint32_t sw = SMEM_SWZ128(n * 128 + o16 * 16);
                cp16(bbase + sw, &g_w16[(size_t)j * HH + k0 + o16 * 8]);
            }
        }
    };
    auto issue_h = [&](const __half* h_in, int c, int s) {
        uint32_t ab0 = sbase + s * STG_BYTES;
#pragma unroll
        for (int s2 = 0; s2 < 2; s2++) {
            int k0 = c * KC + s2 * 64;
            uint32_t abase = ab0 + s2 * ASUB_BYTES;
#pragma unroll
            for (int i = 0; i < 4; i++) {
                int lin = tid + i * STEP_THREADS;
                int row = lin >> 3;
                int o16 = lin & 7;
                uint32_t sw = SMEM_SWZ128(row * 128 + o16 * 16);
                cp16(abase + sw, &h_in[row * HH + k0 + o16 * 8]);
            }
        }
    };
    auto issue_gx = [&](int t) {
        const float* gx = &g_gx2[(((size_t)t * 128 + cb) * 128) * 64];
#pragma unroll
        for (int i = 0; i < 8; i++) {
            int lin = tid + i * STEP_THREADS;
            cp16(sbase + GX_OFF + lin * 16, gx + lin * 4);
        }
    };

    issue_w(0, 0);
    issue_gx(0);
    cp_commit();
    issue_w(1, 1);
    cp_commit();
    issue_h(g_ha, 0, 0);
    cp_commit();
    issue_h(g_ha, 1, 1);
    cp_commit();

    for (int t = 0; t < TT; t++) {
        const __half* __restrict__ h_in = (t & 1) ? g_hb : g_ha;
        __half* __restrict__ h_out = (t & 1) ? g_ha : g_hb;

        float acc[2][4][4] = {};

        for (int kb = 0; kb < NCHUNK; kb++) {
            cp_wait<1>();
            __syncthreads();
            int kn = kb + 2;
            if (kn < NCHUNK) {
                issue_h(h_in, kn, kn % NSTG);
                issue_w(kn, kn % NSTG);
            }
            cp_commit();
            const uint32_t base = sbase + (kb % NSTG) * STG_BYTES;

            uint32_t a[2][2][4], b[2][2][4];
            auto load_frags = [&](int q, int pb) {
                const int ks = q >> 2, qq = q & 3;
                const uint32_t ab = base + ks * ASUB_BYTES;
                const uint32_t bb = base + A_BYTES + ks * BSUB_BYTES;
#pragma unroll
                for (int mt = 0; mt < 2; mt++) {
                    int row = wm + mt * 16 + arow;
                    uint32_t sw = SMEM_SWZ128(row * 128 + (2 * qq + acs) * 16);
                    ldsm4(a[pb][mt], ab + sw);
                }
#pragma unroll
                for (int nh = 0; nh < 2; nh++) {
                    int n = wn + nh * 16 + brow;
                    uint32_t sw = SMEM_SWZ128(n * 128 + (2 * qq + bcs) * 16);
                    ldsm4(b[pb][nh], bb + sw);
                }
            };
            load_frags(0, 0);
#pragma unroll
            for (int q = 0; q < 8; q++) {
                if (q < 7) load_frags(q + 1, (q + 1) & 1);
                const int pb = q & 1;
#pragma unroll
                for (int mt = 0; mt < 2; mt++)
#pragma unroll
                    for (int nt = 0; nt < 4; nt++)
                        mma_fp16(acc[mt][nt], a[pb][mt], b[pb][nt >> 1][(nt & 1) * 2],
                                 b[pb][nt >> 1][(nt & 1) * 2 + 1]);
            }
        }

        float* gsm = reinterpret_cast<float*>(dyn_smem + GSM_OFF);
#pragma unroll
        for (int mt = 0; mt < 2; mt++) {
#pragma unroll
            for (int nt = 0; nt < 4; nt++) {
                int row0 = wm + mt * 16 + g8;
                int col0 = wn + nt * 8 + 2 * tig;
                gsm[row0 * 65 + col0] = acc[mt][nt][0];
                gsm[row0 * 65 + col0 + 1] = acc[mt][nt][1];
                gsm[(row0 + 8) * 65 + col0] = acc[mt][nt][2];
                gsm[(row0 + 8) * 65 + col0 + 1] = acc[mt][nt][3];
            }
        }
        __syncthreads();

        {
            const float* __restrict__ gxs = reinterpret_cast<const float*>(dyn_smem + GX_OFF);
            const int b = tid >> 1;
            const int hh = (tid & 1) * 8;
            float* __restrict__ cc = &g_c2[(cb * 128 + b) * 16 + hh];
            float4 cA = *reinterpret_cast<float4*>(cc);
            float4 cB = *reinterpret_cast<float4*>(cc + 4);
            float cv[8] = {cA.x, cA.y, cA.z, cA.w, cB.x, cB.y, cB.z, cB.w};
            __align__(16) __half hv8[8];
            float hvf[8];
#pragma unroll
            for (int i = 0; i < 8; i++) {
                int hc = hh + i;
                float xi = gsm[b * 65 + 0 * 16 + hc] + gxs[b * 64 + 0 * 16 + hc];
                float xf = gsm[b * 65 + 1 * 16 + hc] + gxs[b * 64 + 1 * 16 + hc];
                float xg = gsm[b * 65 + 2 * 16 + hc] + gxs[b * 64 + 2 * 16 + hc];
                float xo = gsm[b * 65 + 3 * 16 + hc] + gxs[b * 64 + 3 * 16 + hc];
                float ig = sigmoidf_(xi);
                float fg = sigmoidf_(xf);
                float gg = tanhf(xg);
                float og = sigmoidf_(xo);
                float cn = fg * cv[i] + ig * gg;
                cv[i] = cn;
                float hv = og * tanhf(cn);
                hvf[i] = hv;
                hv8[i] = __float2half(hv);
            }
            *reinterpret_cast<float4*>(cc) = make_float4(cv[0], cv[1], cv[2], cv[3]);
            *reinterpret_cast<float4*>(cc + 4) = make_float4(cv[4], cv[5], cv[6], cv[7]);
            *reinterpret_cast<uint4*>(&h_out[b * HH + h0 + hh]) =
                *reinterpret_cast<uint4*>(hv8);
            if (t == TT - 1) {
                *reinterpret_cast<float4*>(&d_out[b * HH + h0 + hh]) =
                    make_float4(hvf[0], hvf[1], hvf[2], hvf[3]);
                *reinterpret_cast<float4*>(&d_out[b * HH + h0 + hh + 4]) =
                    make_float4(hvf[4], hvf[5], hvf[6], hvf[7]);
            }
        }

        if (t < TT - 1) {
            __syncthreads();
            issue_w(0, 0);
            issue_gx(t + 1);
            cp_commit();
            issue_w(1, 1);
            cp_commit();
            __threadfence();
            if (tid == 0) {
                atomicAdd(&g_bar, 1u);
                const unsigned target = 128u * (unsigned)(t + 1);
                unsigned v;
                do {
                    asm volatile("ld.acquire.gpu.global.u32 %0, [%1];" : "=r"(v) : "l"(&g_bar));
                    if (v < target) __nanosleep(64);
                } while (v < target);
            }
            __syncthreads();
            issue_h(h_out, 0, 0);
            cp_commit();
            issue_h(h_out, 1, 1);
            cp_commit();
        }
    }
}

// ---------------- launch ----------------------------------------------------
extern "C" void kernel_launch(void* const* d_in, const int* in_sizes, int n_in, void* d_out,
                              int out_size) {
    const int* input = (const int*)d_in[0];
    const float* embed = (const float*)d_in[1];
    const float* w_ih = (const float*)d_in[2];
    const float* w_hh = (const float*)d_in[3];
    const float* b_ih = (const float*)d_in[4];
    const float* b_hh = (const float*)d_in[5];
    float* out = (float*)d_out;

    cudaFuncSetAttribute(xproj16_kernel, cudaFuncAttributeMaxDynamicSharedMemorySize, XQ_SMEM);
    cudaFuncSetAttribute(step_persistent, cudaFuncAttributeMaxDynamicSharedMemorySize,
                         STEP_SMEM_BYTES);

    zero_kernel<<<(BB * HH + 255) / 256, 256>>>();
    wconv_kernel<<<(int)(((size_t)G4 * HH / 4 + 255) / 256), 256>>>(w_hh);
    gather16_kernel<<<dim3(1024, 2), 256>>>(input, embed, w_ih);
    xproj16_kernel<<<dim3(32, 64), 256, XQ_SMEM>>>(b_ih, b_hh);
    step_persistent<<<128, STEP_THREADS, STEP_SMEM_BYTES>>>(out);
}

// round 14
// speedup vs baseline: 1.7251x; 1.0005x over previous
#include <cuda_runtime.h>
#include <cuda_fp16.h>
#include <cstdint>

#define BB 128          // batch
#define TT 64           // time steps
#define EE 300          // embed dim
#define EP 320          // padded embed dim (5 x 64)
#define HH 2048         // hidden
#define G4 8192         // 4*H

// ---------------- scratch (device globals; no allocation allowed) ----------
__device__ float g_gx2[(size_t)TT * 128 * 128 * 64];   // [t][cb][b][gate*16+hc]
__device__ __half g_w16[(size_t)G4 * HH];              // W_hh fp16
__device__ __half g_x16[(size_t)TT * BB * EP];         // gathered embeddings fp16 (padded)
__device__ __half g_wih16[(size_t)G4 * EP];            // W_ih fp16 (padded)
__device__ __half g_ha[BB * HH];                       // hidden state ping
__device__ __half g_hb[BB * HH];                       // hidden state pong
__device__ float g_c2[BB * HH];                        // cell state [cb][b][16]
__device__ unsigned g_bar;                             // persistent-kernel barrier

// single dynamic smem symbol shared by all kernels
extern __shared__ __align__(1024) char dyn_smem[];

// ---------------- helpers --------------------------------------------------
__device__ __forceinline__ uint32_t smem_u32(const void* p) {
    return (uint32_t)__cvta_generic_to_shared(p);
}
__device__ __forceinline__ void cp16(uint32_t dst, const void* src) {
    asm volatile("cp.async.cg.shared.global [%0], [%1], 16;\n" ::"r"(dst), "l"(src));
}
__device__ __forceinline__ void cp_commit() { asm volatile("cp.async.commit_group;\n"); }
template <int N> __device__ __forceinline__ void cp_wait() {
    asm volatile("cp.async.wait_group %0;\n" ::"n"(N));
}
__device__ __forceinline__ void mma_fp16(float c[4], const uint32_t a[4], uint32_t b0,
                                         uint32_t b1) {
    asm volatile(
        "mma.sync.aligned.m16n8k16.row.col.f32.f16.f16.f32 "
        "{%0,%1,%2,%3},{%4,%5,%6,%7},{%8,%9},{%0,%1,%2,%3};\n"
        : "+f"(c[0]), "+f"(c[1]), "+f"(c[2]), "+f"(c[3])
        : "r"(a[0]), "r"(a[1]), "r"(a[2]), "r"(a[3]), "r"(b0), "r"(b1));
}
__device__ __forceinline__ void ldsm4(uint32_t r[4], uint32_t addr) {
    asm volatile("ldmatrix.sync.aligned.m8n8.x4.shared.b16 {%0,%1,%2,%3}, [%4];"
                 : "=r"(r[0]), "=r"(r[1]), "=r"(r[2]), "=r"(r[3])
                 : "r"(addr));
}
__device__ __forceinline__ float sigmoidf_(float x) { return 1.0f / (1.0f + __expf(-x)); }

#define SMEM_SWZ128(x) ((x) ^ (((x) >> 3) & 0x70))

// ---------------- init / converters -----------------------------------------
__global__ void zero_kernel() {
    int i = blockIdx.x * blockDim.x + threadIdx.x;
    if (i < BB * HH) {
        g_ha[i] = __float2half(0.f);
        g_c2[i] = 0.f;
    }
    if (i == 0) g_bar = 0u;
}

__global__ void wconv_kernel(const float* __restrict__ w) {
    size_t i = ((size_t)blockIdx.x * blockDim.x + threadIdx.x) * 4;
    if (i < (size_t)G4 * HH) {
        float4 v = *reinterpret_cast<const float4*>(w + i);
        g_w16[i] = __float2half(v.x);
        g_w16[i + 1] = __float2half(v.y);
        g_w16[i + 2] = __float2half(v.z);
        g_w16[i + 3] = __float2half(v.w);
    }
}

// gather embeddings + convert w_ih to fp16 (rows padded 300 -> 320 with zeros)
__global__ void __launch_bounds__(256) gather16_kernel(const int* __restrict__ input,
                                                       const float* __restrict__ embed,
                                                       const float* __restrict__ w_ih) {
    const int wid = threadIdx.x >> 5, lane = threadIdx.x & 31;
    const int row = blockIdx.x * 8 + wid;  // 0..8191
    if (blockIdx.y == 0) {
        const int t = row >> 7, b = row & 127;
        const int tok = input[b * TT + t];
        const float* __restrict__ src = embed + (size_t)tok * EE;
        __half* __restrict__ dst = g_x16 + (size_t)row * EP;
        for (int c = lane; c < EP; c += 32)
            dst[c] = (c < EE) ? __float2half(src[c]) : __float2half(0.f);
    } else {
        const float* __restrict__ src = w_ih + (size_t)row * EE;
        __half* __restrict__ dst = g_wih16 + (size_t)row * EP;
        for (int c = lane; c < EP; c += 32)
            dst[c] = (c < EE) ? __float2half(src[c]) : __float2half(0.f);
    }
}

// ---------------- kernel 1: input projection, fp16 tensor path --------------
// grid (32, 64): BM=256 rows (2 t x 128 b), BN=128 cols. 512 threads = 16
// warps (4M x 4N), warp tile 64x32. K = 320 in 5 chunks of 64.
#define XQ_KC 64
#define XQ_NCH (EP / XQ_KC)                    // 5
#define XQ_AT (256 * 128)                      // A tile 32 KB
#define XQ_BT (128 * 128)                      // B tile 16 KB
#define XQ_STG (XQ_AT + XQ_BT)                 // 49152
#define XQ_NSTG 3
#define XQ_SMEM (XQ_NSTG * XQ_STG)             // 147456
#define XQ_THREADS 512

__global__ void __launch_bounds__(XQ_THREADS) xproj16_kernel(const float* __restrict__ b_ih,
                                                             const float* __restrict__ b_hh) {
    const uint32_t sbase = smem_u32(dyn_smem);
    const int tid = threadIdx.x;
    const int wid = tid >> 5, lane = tid & 31;
    const int m0 = blockIdx.x * 256;
    const int n0 = blockIdx.y * 128;
    const int wm = (wid & 3) * 64, wn = (wid >> 2) * 32;

    const int arow = lane & 15;
    const int acs = lane >> 4;
    const int brow = (lane & 7) + ((lane & 16) >> 1);
    const int bcs = (lane >> 3) & 1;
    const int g8 = lane >> 2, tig = lane & 3;

    auto issue_stage = [&](int c, int s) {
        uint32_t base = sbase + s * XQ_STG;
        int k0 = c * XQ_KC;
#pragma unroll
        for (int i = 0; i < 4; i++) {
            int lin = tid + i * XQ_THREADS;
            int row = lin >> 3;
            int o16 = lin & 7;
            uint32_t sw = SMEM_SWZ128(row * 128 + o16 * 16);
            cp16(base + sw, &g_x16[(size_t)(m0 + row) * EP + k0 + o16 * 8]);
        }
#pragma unroll
        for (int i = 0; i < 2; i++) {
            int lin = tid + i * XQ_THREADS;
            int n = lin >> 3;
            int o16 = lin & 7;
            uint32_t sw = SMEM_SWZ128(n * 128 + o16 * 16);
            cp16(base + XQ_AT + sw, &g_wih16[(size_t)(n0 + n) * EP + k0 + o16 * 8]);
        }
        cp_commit();
    };

    float acc[4][4][4] = {};

    issue_stage(0, 0);
    issue_stage(1, 1);

    for (int kb = 0; kb < XQ_NCH; kb++) {
        cp_wait<1>();
        __syncthreads();
        int kn = kb + 2;
        if (kn < XQ_NCH) issue_stage(kn, kn % XQ_NSTG);
        else cp_commit();
        const uint32_t base = sbase + (kb % XQ_NSTG) * XQ_STG;

#pragma unroll
        for (int q = 0; q < 4; q++) {
            uint32_t a[4][4], b[2][4];
#pragma unroll
            for (int mt = 0; mt < 4; mt++) {
                int row = wm + mt * 16 + arow;
                uint32_t sw = SMEM_SWZ128(row * 128 + (2 * q + acs) * 16);
                ldsm4(a[mt], base + sw);
            }
#pragma unroll
            for (int nh = 0; nh < 2; nh++) {
                int n = wn + nh * 16 + brow;
                uint32_t sw = SMEM_SWZ128(n * 128 + (2 * q + bcs) * 16);
                ldsm4(b[nh], base + XQ_AT + sw);
            }
#pragma unroll
            for (int mt = 0; mt < 4; mt++)
#pragma unroll
                for (int nt = 0; nt < 4; nt++)
                    mma_fp16(acc[mt][nt], a[mt], b[nt >> 1][(nt & 1) * 2],
                             b[nt >> 1][(nt & 1) * 2 + 1]);
        }
    }

    // epilogue: add biases, write g_gx2[t][cb][b][gate*16+hc]
#pragma unroll
    for (int mt = 0; mt < 4; mt++) {
#pragma unroll
        for (int nt = 0; nt < 4; nt++) {
            int row0 = wm + mt * 16 + g8;
            int col0 = wn + nt * 8 + 2 * tig;
            int rg = m0 + row0;
            int t = rg >> 7, b = rg & 127;
            int j0 = n0 + col0;
            int gate = j0 >> 11;
            int qq = j0 & 2047;
            int cb = qq >> 4;
            int hc = qq & 15;
            float bias0 = b_ih[j0] + b_hh[j0];
            float bias1 = b_ih[j0 + 1] + b_hh[j0 + 1];
            size_t base0 = (((size_t)t * 128 + cb) * 128 + b) * 64 + gate * 16 + hc;
            g_gx2[base0] = acc[mt][nt][0] + bias0;
            g_gx2[base0 + 1] = acc[mt][nt][1] + bias1;
            size_t base2 = base0 + 8 * 64;
            g_gx2[base2] = acc[mt][nt][2] + bias0;
            g_gx2[base2 + 1] = acc[mt][nt][3] + bias1;
        }
    }
}

// ---------------- kernel 2: persistent fp16 LSTM (all 64 steps) -------------
// (unchanged champion from round 12)
#define KC 128
#define NCHUNK (HH / KC)                       // 16
#define ASUB_BYTES (128 * 128)                 // A sub-tile 16 KB
#define BSUB_BYTES (64 * 128)                  // B sub-tile 8 KB
#define A_BYTES (2 * ASUB_BYTES)               // 32 KB per stage
#define STG_BYTES (A_BYTES + 2 * BSUB_BYTES)   // 49152
#define NSTG 3
#define GX_OFF (NSTG * STG_BYTES)              // 147456
#define GSM_OFF (GX_OFF + 128 * 64 * 4)        // 180224
#define STEP_SMEM_BYTES (GSM_OFF + 128 * 65 * 4)  // 213504
#define STEP_THREADS 256

__global__ void __launch_bounds__(STEP_THREADS) step_persistent(float* __restrict__ d_out) {
    const uint32_t sbase = smem_u32(dyn_smem);
    const int tid = threadIdx.x;
    const int wid = tid >> 5, lane = tid & 31;
    const int cb = blockIdx.x;
    const int h0 = cb * 16;
    const int wm = (wid & 3) * 32, wn = (wid >> 2) * 32;

    const int arow = lane & 15;
    const int acs = lane >> 4;
    const int brow = (lane & 7) + ((lane & 16) >> 1);
    const int bcs = (lane >> 3) & 1;
    const int g8 = lane >> 2, tig = lane & 3;

    auto issue_w = [&](int c, int s) {
        uint32_t bb0 = sbase + s * STG_BYTES + A_BYTES;
#pragma unroll
        for (int s2 = 0; s2 < 2; s2++) {
            int k0 = c * KC + s2 * 64;
            uint32_t bbase = bb0 + s2 * BSUB_BYTES;
#pragma unroll
            for (int i = 0; i < 2; i++) {
                int lin = tid + i * STEP_THREADS;
                int n = lin >> 3;
                int o16 = lin & 7;
                int j = (n >> 4) * HH + h0 + (n & 15);
                uint32_t sw = SMEM_SWZ128(n * 128 + o16 * 16);
                cp16(bbase + sw, &g_w16[(size_t)j * HH + k0 + o16 * 8]);
            }
        }
    };
    auto issue_h = [&](const __half* h_in, int c, int s) {
        uint32_t ab0 = sbase + s * STG_BYTES;
#pragma unroll
        for (int s2 = 0; s2 < 2; s2++) {
            int k0 = c * KC + s2 * 64;
            uint32_t abase = ab0 + s2 * ASUB_BYTES;
#pragma unroll
            for (int i = 0; i < 4; i++) {
                int lin = tid + i * STEP_THREADS;
                int row = lin >> 3;
                int o16 = lin & 7;
                uint32_t sw = SMEM_SWZ128(row * 128 + o16 * 16);
                cp16(abase + sw, &h_in[row * HH + k0 + o16 * 8]);
            }
        }
    };
    auto issue_gx = [&](int t) {
        const float* gx = &g_gx2[(((size_t)t * 128 + cb) * 128) * 64];
#pragma unroll
        for (int i = 0; i < 8; i++) {
            int lin = tid + i * STEP_THREADS;
            cp16(sbase + GX_OFF + lin * 16, gx + lin * 4);
        }
    };

    issue_w(0, 0);
    issue_gx(0);
    cp_commit();
    issue_w(1, 1);
    cp_commit();
    issue_h(g_ha, 0, 0);
    cp_commit();
    issue_h(g_ha, 1, 1);
    cp_commit();

    for (int t = 0; t < TT; t++) {
        const __half* __restrict__ h_in = (t & 1) ? g_hb : g_ha;
        __half* __restrict__ h_out = (t & 1) ? g_ha : g_hb;

        float acc[2][4][4] = {};

        for (int kb = 0; kb < NCHUNK; kb++) {
            cp_wait<1>();
            __syncthreads();
            int kn = kb + 2;
            if (kn < NCHUNK) {
                issue_h(h_in, kn, kn % NSTG);
                issue_w(kn, kn % NSTG);
            }
            cp_commit();
            const uint32_t base = sbase + (kb % NSTG) * STG_BYTES;

            uint32_t a[2][2][4], b[2][2][4];
            auto load_frags = [&](int q, int pb) {
                const int ks = q >> 2, qq = q & 3;
                const uint32_t ab = base + ks * ASUB_BYTES;
                const uint32_t bb = base + A_BYTES + ks * BSUB_BYTES;
#pragma unroll
                for (int mt = 0; mt < 2; mt++) {
                    int row = wm + mt * 16 + arow;
                    uint32_t sw = SMEM_SWZ128(row * 128 + (2 * qq + acs) * 16);
                    ldsm4(a[pb][mt], ab + sw);
                }
#pragma unroll
                for (int nh = 0; nh < 2; nh++) {
                    int n = wn + nh * 16 + brow;
                    uint32_t sw = SMEM_SWZ128(n * 128 + (2 * qq + bcs) * 16);
                    ldsm4(b[pb][nh], bb + sw);
                }
            };
            load_frags(0, 0);
#pragma unroll
            for (int q = 0; q < 8; q++) {
                if (q < 7) load_frags(q + 1, (q + 1) & 1);
                const int pb = q & 1;
#pragma unroll
                for (int mt = 0; mt < 2; mt++)
#pragma unroll
                    for (int nt = 0; nt < 4; nt++)
                        mma_fp16(acc[mt][nt], a[pb][mt], b[pb][nt >> 1][(nt & 1) * 2],
                                 b[pb][nt >> 1][(nt & 1) * 2 + 1]);
            }
        }

        float* gsm = reinterpret_cast<float*>(dyn_smem + GSM_OFF);
#pragma unroll
        for (int mt = 0; mt < 2; mt++) {
#pragma unroll
            for (int nt = 0; nt < 4; nt++) {
                int row0 = wm + mt * 16 + g8;
                int col0 = wn + nt * 8 + 2 * tig;
                gsm[row0 * 65 + col0] = acc[mt][nt][0];
                gsm[row0 * 65 + col0 + 1] = acc[mt][nt][1];
                gsm[(row0 + 8) * 65 + col0] = acc[mt][nt][2];
                gsm[(row0 + 8) * 65 + col0 + 1] = acc[mt][nt][3];
            }
        }
        __syncthreads();

        {
            const float* __restrict__ gxs = reinterpret_cast<const float*>(dyn_smem + GX_OFF);
            const int b = tid >> 1;
            const int hh = (tid & 1) * 8;
            float* __restrict__ cc = &g_c2[(cb * 128 + b) * 16 + hh];
            float4 cA = *reinterpret_cast<float4*>(cc);
            float4 cB = *reinterpret_cast<float4*>(cc + 4);
            float cv[8] = {cA.x, cA.y, cA.z, cA.w, cB.x, cB.y, cB.z, cB.w};
            __align__(16) __half hv8[8];
            float hvf[8];
#pragma unroll
            for (int i = 0; i < 8; i++) {
                int hc = hh + i;
                float xi = gsm[b * 65 + 0 * 16 + hc] + gxs[b * 64 + 0 * 16 + hc];
                float xf = gsm[b * 65 + 1 * 16 + hc] + gxs[b * 64 + 1 * 16 + hc];
                float xg = gsm[b * 65 + 2 * 16 + hc] + gxs[b * 64 + 2 * 16 + hc];
                float xo = gsm[b * 65 + 3 * 16 + hc] + gxs[b * 64 + 3 * 16 + hc];
                float ig = sigmoidf_(xi);
                float fg = sigmoidf_(xf);
                float gg = tanhf(xg);
                float og = sigmoidf_(xo);
                float cn = fg * cv[i] + ig * gg;
                cv[i] = cn;
                float hv = og * tanhf(cn);
                hvf[i] = hv;
                hv8[i] = __float2half(hv);
            }
            *reinterpret_cast<float4*>(cc) = make_float4(cv[0], cv[1], cv[2], cv[3]);
            *reinterpret_cast<float4*>(cc + 4) = make_float4(cv[4], cv[5], cv[6], cv[7]);
            *reinterpret_cast<uint4*>(&h_out[b * HH + h0 + hh]) =
                *reinterpret_cast<uint4*>(hv8);
            if (t == TT - 1) {
                *reinterpret_cast<float4*>(&d_out[b * HH + h0 + hh]) =
                    make_float4(hvf[0], hvf[1], hvf[2], hvf[3]);
                *reinterpret_cast<float4*>(&d_out[b * HH + h0 + hh + 4]) =
                    make_float4(hvf[4], hvf[5], hvf[6], hvf[7]);
            }
        }

        if (t < TT - 1) {
            __syncthreads();
            issue_w(0, 0);
            issue_gx(t + 1);
            cp_commit();
            issue_w(1, 1);
            cp_commit();
            __threadfence();
            if (tid == 0) {
                atomicAdd(&g_bar, 1u);
                const unsigned target = 128u * (unsigned)(t + 1);
                unsigned v;
                do {
                    asm volatile("ld.acquire.gpu.global.u32 %0, [%1];" : "=r"(v) : "l"(&g_bar));
                    if (v < target) __nanosleep(64);
                } while (v < target);
            }
            __syncthreads();
            issue_h(h_out, 0, 0);
            cp_commit();
            issue_h(h_out, 1, 1);
            cp_commit();
        }
    }
}

// ---------------- launch ----------------------------------------------------
extern "C" void kernel_launch(void* const* d_in, const int* in_sizes, int n_in, void* d_out,
                              int out_size) {
    const int* input = (const int*)d_in[0];
    const float* embed = (const float*)d_in[1];
    const float* w_ih = (const float*)d_in[2];
    const float* w_hh = (const float*)d_in[3];
    const float* b_ih = (const float*)d_in[4];
    const float* b_hh = (const float*)d_in[5];
    float* out = (float*)d_out;

    cudaFuncSetAttribute(xproj16_kernel, cudaFuncAttributeMaxDynamicSharedMemorySize, XQ_SMEM);
    cudaFuncSetAttribute(step_persistent, cudaFuncAttributeMaxDynamicSharedMemorySize,
                         STEP_SMEM_BYTES);

    zero_kernel<<<(BB * HH + 255) / 256, 256>>>();
    wconv_kernel<<<(int)(((size_t)G4 * HH / 4 + 255) / 256), 256>>>(w_hh);
    gather16_kernel<<<dim3(1024, 2), 256>>>(input, embed, w_ih);
    xproj16_kernel<<<dim3(32, 64), XQ_THREADS, XQ_SMEM>>>(b_ih, b_hh);
    step_persistent<<<128, STEP_THREADS, STEP_SMEM_BYTES>>>(out);
}

// round 15
// speedup vs baseline: 1.8038x; 1.0456x over previous
#include <cuda_runtime.h>
#include <cuda_fp16.h>
#include <cstdint>

#define BB 128          // batch
#define TT 64           // time steps
#define EE 300          // embed dim
#define EP 320          // padded embed dim (5 x 64)
#define HH 2048         // hidden
#define G4 8192         // 4*H

// ---------------- scratch (device globals; no allocation allowed) ----------
__device__ __half g_gxh[(size_t)TT * 128 * 128 * 64];  // [t][cb][b][gate*16+hc] fp16
__device__ __half g_w16[(size_t)G4 * HH];              // W_hh fp16
__device__ __half g_x16[(size_t)TT * BB * EP];         // gathered embeddings fp16 (padded)
__device__ __half g_wih16[(size_t)G4 * EP];            // W_ih fp16 (padded)
__device__ __half g_ha[BB * HH];                       // hidden state ping
__device__ __half g_hb[BB * HH];                       // hidden state pong
__device__ float g_c2[BB * HH];                        // cell state [cb][b][16]
__device__ unsigned g_bar;                             // persistent-kernel barrier

// single dynamic smem symbol shared by all kernels
extern __shared__ __align__(1024) char dyn_smem[];

// ---------------- helpers --------------------------------------------------
__device__ __forceinline__ uint32_t smem_u32(const void* p) {
    return (uint32_t)__cvta_generic_to_shared(p);
}
__device__ __forceinline__ void cp16(uint32_t dst, const void* src) {
    asm volatile("cp.async.cg.shared.global [%0], [%1], 16;\n" ::"r"(dst), "l"(src));
}
__device__ __forceinline__ void cp_commit() { asm volatile("cp.async.commit_group;\n"); }
template <int N> __device__ __forceinline__ void cp_wait() {
    asm volatile("cp.async.wait_group %0;\n" ::"n"(N));
}
__device__ __forceinline__ void mma_fp16(float c[4], const uint32_t a[4], uint32_t b0,
                                         uint32_t b1) {
    asm volatile(
        "mma.sync.aligned.m16n8k16.row.col.f32.f16.f16.f32 "
        "{%0,%1,%2,%3},{%4,%5,%6,%7},{%8,%9},{%0,%1,%2,%3};\n"
        : "+f"(c[0]), "+f"(c[1]), "+f"(c[2]), "+f"(c[3])
        : "r"(a[0]), "r"(a[1]), "r"(a[2]), "r"(a[3]), "r"(b0), "r"(b1));
}
__device__ __forceinline__ void ldsm4(uint32_t r[4], uint32_t addr) {
    asm volatile("ldmatrix.sync.aligned.m8n8.x4.shared.b16 {%0,%1,%2,%3}, [%4];"
                 : "=r"(r[0]), "=r"(r[1]), "=r"(r[2]), "=r"(r[3])
                 : "r"(addr));
}
__device__ __forceinline__ float sigmoidf_(float x) { return 1.0f / (1.0f + __expf(-x)); }

#define SMEM_SWZ128(x) ((x) ^ (((x) >> 3) & 0x70))

// ---------------- init / converters -----------------------------------------
__global__ void zero_kernel() {
    int i = blockIdx.x * blockDim.x + threadIdx.x;
    if (i < BB * HH) {
        g_ha[i] = __float2half(0.f);
        g_c2[i] = 0.f;
    }
    if (i == 0) g_bar = 0u;
}

__global__ void wconv_kernel(const float* __restrict__ w) {
    size_t i = ((size_t)blockIdx.x * blockDim.x + threadIdx.x) * 4;
    if (i < (size_t)G4 * HH) {
        float4 v = *reinterpret_cast<const float4*>(w + i);
        g_w16[i] = __float2half(v.x);
        g_w16[i + 1] = __float2half(v.y);
        g_w16[i + 2] = __float2half(v.z);
        g_w16[i + 3] = __float2half(v.w);
    }
}

// gather embeddings + convert w_ih to fp16 (rows padded 300 -> 320 with zeros)
__global__ void __launch_bounds__(256) gather16_kernel(const int* __restrict__ input,
                                                       const float* __restrict__ embed,
                                                       const float* __restrict__ w_ih) {
    const int wid = threadIdx.x >> 5, lane = threadIdx.x & 31;
    const int row = blockIdx.x * 8 + wid;  // 0..8191
    if (blockIdx.y == 0) {
        const int t = row >> 7, b = row & 127;
        const int tok = input[b * TT + t];
        const float* __restrict__ src = embed + (size_t)tok * EE;
        __half* __restrict__ dst = g_x16 + (size_t)row * EP;
        for (int c = lane; c < EP; c += 32)
            dst[c] = (c < EE) ? __float2half(src[c]) : __float2half(0.f);
    } else {
        const float* __restrict__ src = w_ih + (size_t)row * EE;
        __half* __restrict__ dst = g_wih16 + (size_t)row * EP;
        for (int c = lane; c < EP; c += 32)
            dst[c] = (c < EE) ? __float2half(src[c]) : __float2half(0.f);
    }
}

// ---------------- kernel 1: input projection, fp16 tensor path --------------
// grid (32, 64): BM=256 rows (2 t x 128 b), BN=128 cols. 512 threads = 16
// warps (4M x 4N), warp tile 64x32. K = 320 in 5 chunks of 64. Output fp16.
#define XQ_KC 64
#define XQ_NCH (EP / XQ_KC)                    // 5
#define XQ_AT (256 * 128)                      // A tile 32 KB
#define XQ_BT (128 * 128)                      // B tile 16 KB
#define XQ_STG (XQ_AT + XQ_BT)                 // 49152
#define XQ_NSTG 3
#define XQ_SMEM (XQ_NSTG * XQ_STG)             // 147456
#define XQ_THREADS 512

__global__ void __launch_bounds__(XQ_THREADS) xproj16_kernel(const float* __restrict__ b_ih,
                                                             const float* __restrict__ b_hh) {
    const uint32_t sbase = smem_u32(dyn_smem);
    const int tid = threadIdx.x;
    const int wid = tid >> 5, lane = tid & 31;
    const int m0 = blockIdx.x * 256;
    const int n0 = blockIdx.y * 128;
    const int wm = (wid & 3) * 64, wn = (wid >> 2) * 32;

    const int arow = lane & 15;
    const int acs = lane >> 4;
    const int brow = (lane & 7) + ((lane & 16) >> 1);
    const int bcs = (lane >> 3) & 1;
    const int g8 = lane >> 2, tig = lane & 3;

    auto issue_stage = [&](int c, int s) {
        uint32_t base = sbase + s * XQ_STG;
        int k0 = c * XQ_KC;
#pragma unroll
        for (int i = 0; i < 4; i++) {
            int lin = tid + i * XQ_THREADS;
            int row = lin >> 3;
            int o16 = lin & 7;
            uint32_t sw = SMEM_SWZ128(row * 128 + o16 * 16);
            cp16(base + sw, &g_x16[(size_t)(m0 + row) * EP + k0 + o16 * 8]);
        }
#pragma unroll
        for (int i = 0; i < 2; i++) {
            int lin = tid + i * XQ_THREADS;
            int n = lin >> 3;
            int o16 = lin & 7;
            uint32_t sw = SMEM_SWZ128(n * 128 + o16 * 16);
            cp16(base + XQ_AT + sw, &g_wih16[(size_t)(n0 + n) * EP + k0 + o16 * 8]);
        }
        cp_commit();
    };

    float acc[4][4][4] = {};

    issue_stage(0, 0);
    issue_stage(1, 1);

    for (int kb = 0; kb < XQ_NCH; kb++) {
        cp_wait<1>();
        __syncthreads();
        int kn = kb + 2;
        if (kn < XQ_NCH) issue_stage(kn, kn % XQ_NSTG);
        else cp_commit();
        const uint32_t base = sbase + (kb % XQ_NSTG) * XQ_STG;

#pragma unroll
        for (int q = 0; q < 4; q++) {
            uint32_t a[4][4], b[2][4];
#pragma unroll
            for (int mt = 0; mt < 4; mt++) {
                int row = wm + mt * 16 + arow;
                uint32_t sw = SMEM_SWZ128(row * 128 + (2 * q + acs) * 16);
                ldsm4(a[mt], base + sw);
            }
#pragma unroll
            for (int nh = 0; nh < 2; nh++) {
                int n = wn + nh * 16 + brow;
                uint32_t sw = SMEM_SWZ128(n * 128 + (2 * q + bcs) * 16);
                ldsm4(b[nh], base + XQ_AT + sw);
            }
#pragma unroll
            for (int mt = 0; mt < 4; mt++)
#pragma unroll
                for (int nt = 0; nt < 4; nt++)
                    mma_fp16(acc[mt][nt], a[mt], b[nt >> 1][(nt & 1) * 2],
                             b[nt >> 1][(nt & 1) * 2 + 1]);
        }
    }

    // epilogue: add biases, write g_gxh[t][cb][b][gate*16+hc] as __half2 pairs
#pragma unroll
    for (int mt = 0; mt < 4; mt++) {
#pragma unroll
        for (int nt = 0; nt < 4; nt++) {
            int row0 = wm + mt * 16 + g8;
            int col0 = wn + nt * 8 + 2 * tig;
            int rg = m0 + row0;
            int t = rg >> 7, b = rg & 127;
            int j0 = n0 + col0;
            int gate = j0 >> 11;
            int qq = j0 & 2047;
            int cb = qq >> 4;
            int hc = qq & 15;
            float bias0 = b_ih[j0] + b_hh[j0];
            float bias1 = b_ih[j0 + 1] + b_hh[j0 + 1];
            size_t base0 = (((size_t)t * 128 + cb) * 128 + b) * 64 + gate * 16 + hc;
            *reinterpret_cast<__half2*>(&g_gxh[base0]) =
                __floats2half2_rn(acc[mt][nt][0] + bias0, acc[mt][nt][1] + bias1);
            size_t base2 = base0 + 8 * 64;
            *reinterpret_cast<__half2*>(&g_gxh[base2]) =
                __floats2half2_rn(acc[mt][nt][2] + bias0, acc[mt][nt][3] + bias1);
        }
    }
}

// ---------------- kernel 2: persistent fp16 LSTM (all 64 steps) -------------
// champion structure; gx now fp16 (16KB smem buffer, converted in the cell)
#define KC 128
#define NCHUNK (HH / KC)                       // 16
#define ASUB_BYTES (128 * 128)                 // A sub-tile 16 KB
#define BSUB_BYTES (64 * 128)                  // B sub-tile 8 KB
#define A_BYTES (2 * ASUB_BYTES)               // 32 KB per stage
#define STG_BYTES (A_BYTES + 2 * BSUB_BYTES)   // 49152
#define NSTG 3
#define GX_OFF (NSTG * STG_BYTES)              // 147456
#define GSM_OFF (GX_OFF + 128 * 64 * 2)        // 163840
#define STEP_SMEM_BYTES (GSM_OFF + 128 * 65 * 4)  // 197120
#define STEP_THREADS 256

__global__ void __launch_bounds__(STEP_THREADS) step_persistent(float* __restrict__ d_out) {
    const uint32_t sbase = smem_u32(dyn_smem);
    const int tid = threadIdx.x;
    const int wid = tid >> 5, lane = tid & 31;
    const int cb = blockIdx.x;
    const int h0 = cb * 16;
    const int wm = (wid & 3) * 32, wn = (wid >> 2) * 32;

    const int arow = lane & 15;
    const int acs = lane >> 4;
    const int brow = (lane & 7) + ((lane & 16) >> 1);
    const int bcs = (lane >> 3) & 1;
    const int g8 = lane >> 2, tig = lane & 3;

    auto issue_w = [&](int c, int s) {
        uint32_t bb0 = sbase + s * STG_BYTES + A_BYTES;
#pragma unroll
        for (int s2 = 0; s2 < 2; s2++) {
            int k0 = c * KC + s2 * 64;
            uint32_t bbase = bb0 + s2 * BSUB_BYTES;
#pragma unroll
            for (int i = 0; i < 2; i++) {
                int lin = tid + i * STEP_THREADS;
                int n = lin >> 3;
                int o16 = lin & 7;
                int j = (n >> 4) * HH + h0 + (n & 15);
                uint32_t sw = SMEM_SWZ128(n * 128 + o16 * 16);
                cp16(bbase + sw, &g_w16[(size_t)j * HH + k0 + o16 * 8]);
            }
        }
    };
    auto issue_h = [&](const __half* h_in, int c, int s) {
        uint32_t ab0 = sbase + s * STG_BYTES;
#pragma unroll
        for (int s2 = 0; s2 < 2; s2++) {
            int k0 = c * KC + s2 * 64;
            uint32_t abase = ab0 + s2 * ASUB_BYTES;
#pragma unroll
            for (int i = 0; i < 4; i++) {
                int lin = tid + i * STEP_THREADS;
                int row = lin >> 3;
                int o16 = lin & 7;
                uint32_t sw = SMEM_SWZ128(row * 128 + o16 * 16);
                cp16(abase + sw, &h_in[row * HH + k0 + o16 * 8]);
            }
        }
    };
    auto issue_gx = [&](int t) {
        const __half* gx = &g_gxh[(((size_t)t * 128 + cb) * 128) * 64];
#pragma unroll
        for (int i = 0; i < 4; i++) {
            int lin = tid + i * STEP_THREADS;
            cp16(sbase + GX_OFF + lin * 16, gx + lin * 8);
        }
    };

    issue_w(0, 0);
    issue_gx(0);
    cp_commit();
    issue_w(1, 1);
    cp_commit();
    issue_h(g_ha, 0, 0);
    cp_commit();
    issue_h(g_ha, 1, 1);
    cp_commit();

    for (int t = 0; t < TT; t++) {
        const __half* __restrict__ h_in = (t & 1) ? g_hb : g_ha;
        __half* __restrict__ h_out = (t & 1) ? g_ha : g_hb;

        float acc[2][4][4] = {};

        for (int kb = 0; kb < NCHUNK; kb++) {
            cp_wait<1>();
            __syncthreads();
            int kn = kb + 2;
            if (kn < NCHUNK) {
                issue_h(h_in, kn, kn % NSTG);
                issue_w(kn, kn % NSTG);
            }
            cp_commit();
            const uint32_t base = sbase + (kb % NSTG) * STG_BYTES;

            uint32_t a[2][2][4], b[2][2][4];
            auto load_frags = [&](int q, int pb) {
                const int ks = q >> 2, qq = q & 3;
                const uint32_t ab = base + ks * ASUB_BYTES;
                const uint32_t bb = base + A_BYTES + ks * BSUB_BYTES;
#pragma unroll
                for (int mt = 0; mt < 2; mt++) {
                    int row = wm + mt * 16 + arow;
                    uint32_t sw = SMEM_SWZ128(row * 128 + (2 * qq + acs) * 16);
                    ldsm4(a[pb][mt], ab + sw);
                }
#pragma unroll
                for (int nh = 0; nh < 2; nh++) {
                    int n = wn + nh * 16 + brow;
                    uint32_t sw = SMEM_SWZ128(n * 128 + (2 * qq + bcs) * 16);
                    ldsm4(b[pb][nh], bb + sw);
                }
            };
            load_frags(0, 0);
#pragma unroll
            for (int q = 0; q < 8; q++) {
                if (q < 7) load_frags(q + 1, (q + 1) & 1);
                const int pb = q & 1;
#pragma unroll
                for (int mt = 0; mt < 2; mt++)
#pragma unroll
                    for (int nt = 0; nt < 4; nt++)
                        mma_fp16(acc[mt][nt], a[pb][mt], b[pb][nt >> 1][(nt & 1) * 2],
                                 b[pb][nt >> 1][(nt & 1) * 2 + 1]);
            }
        }

        float* gsm = reinterpret_cast<float*>(dyn_smem + GSM_OFF);
#pragma unroll
        for (int mt = 0; mt < 2; mt++) {
#pragma unroll
            for (int nt = 0; nt < 4; nt++) {
                int row0 = wm + mt * 16 + g8;
                int col0 = wn + nt * 8 + 2 * tig;
                gsm[row0 * 65 + col0] = acc[mt][nt][0];
                gsm[row0 * 65 + col0 + 1] = acc[mt][nt][1];
                gsm[(row0 + 8) * 65 + col0] = acc[mt][nt][2];
                gsm[(row0 + 8) * 65 + col0 + 1] = acc[mt][nt][3];
            }
        }
        __syncthreads();

        {
            const __half* __restrict__ gxs =
                reinterpret_cast<const __half*>(dyn_smem + GX_OFF);
            const int b = tid >> 1;
            const int hh = (tid & 1) * 8;
            float* __restrict__ cc = &g_c2[(cb * 128 + b) * 16 + hh];
            float4 cA = *reinterpret_cast<float4*>(cc);
            float4 cB = *reinterpret_cast<float4*>(cc + 4);
            float cv[8] = {cA.x, cA.y, cA.z, cA.w, cB.x, cB.y, cB.z, cB.w};
            __align__(16) __half hv8[8];
            float hvf[8];
#pragma unroll
            for (int i = 0; i < 8; i++) {
                int hc = hh + i;
                float xi = gsm[b * 65 + 0 * 16 + hc] + __half2float(gxs[b * 64 + 0 * 16 + hc]);
                float xf = gsm[b * 65 + 1 * 16 + hc] + __half2float(gxs[b * 64 + 1 * 16 + hc]);
                float xg = gsm[b * 65 + 2 * 16 + hc] + __half2float(gxs[b * 64 + 2 * 16 + hc]);
                float xo = gsm[b * 65 + 3 * 16 + hc] + __half2float(gxs[b * 64 + 3 * 16 + hc]);
                float ig = sigmoidf_(xi);
                float fg = sigmoidf_(xf);
                float gg = tanhf(xg);
                float og = sigmoidf_(xo);
                float cn = fg * cv[i] + ig * gg;
                cv[i] = cn;
                float hv = og * tanhf(cn);
                hvf[i] = hv;
                hv8[i] = __float2half(hv);
            }
            *reinterpret_cast<float4*>(cc) = make_float4(cv[0], cv[1], cv[2], cv[3]);
            *reinterpret_cast<float4*>(cc + 4) = make_float4(cv[4], cv[5], cv[6], cv[7]);
            *reinterpret_cast<uint4*>(&h_out[b * HH + h0 + hh]) =
                *reinterpret_cast<uint4*>(hv8);
            if (t == TT - 1) {
                *reinterpret_cast<float4*>(&d_out[b * HH + h0 + hh]) =
                    make_float4(hvf[0], hvf[1], hvf[2], hvf[3]);
                *reinterpret_cast<float4*>(&d_out[b * HH + h0 + hh + 4]) =
                    make_float4(hvf[4], hvf[5], hvf[6], hvf[7]);
            }
        }

        if (t < TT - 1) {
            __syncthreads();
            issue_w(0, 0);
            issue_gx(t + 1);
            cp_commit();
            issue_w(1, 1);
            cp_commit();
            __threadfence();
            if (tid == 0) {
                atomicAdd(&g_bar, 1u);
                const unsigned target = 128u * (unsigned)(t + 1);
                unsigned v;
                do {
                    asm volatile("ld.acquire.gpu.global.u32 %0, [%1];" : "=r"(v) : "l"(&g_bar));
                    if (v < target) __nanosleep(64);
                } while (v < target);
            }
            __syncthreads();
            issue_h(h_out, 0, 0);
            cp_commit();
            issue_h(h_out, 1, 1);
            cp_commit();
        }
    }
}

// ---------------- launch ----------------------------------------------------
extern "C" void kernel_launch(void* const* d_in, const int* in_sizes, int n_in, void* d_out,
                              int out_size) {
    const int* input = (const int*)d_in[0];
    const float* embed = (const float*)d_in[1];
    const float* w_ih = (const float*)d_in[2];
    const float* w_hh = (const float*)d_in[3];
    const float* b_ih = (const float*)d_in[4];
    const float* b_hh = (const float*)d_in[5];
    float* out = (float*)d_out;

    cudaFuncSetAttribute(xproj16_kernel, cudaFuncAttributeMaxDynamicSharedMemorySize, XQ_SMEM);
    cudaFuncSetAttribute(step_persistent, cudaFuncAttributeMaxDynamicSharedMemorySize,
                         STEP_SMEM_BYTES);

    zero_kernel<<<(BB * HH + 255) / 256, 256>>>();
    wconv_kernel<<<(int)(((size_t)G4 * HH / 4 + 255) / 256), 256>>>(w_hh);
    gather16_kernel<<<dim3(1024, 2), 256>>>(input, embed, w_ih);
    xproj16_kernel<<<dim3(32, 64), XQ_THREADS, XQ_SMEM>>>(b_ih, b_hh);
    step_persistent<<<128, STEP_THREADS, STEP_SMEM_BYTES>>>(out);
}

// round 16
// speedup vs baseline: 1.8381x; 1.0190x over previous
#include <cuda_runtime.h>
#include <cuda_fp16.h>
#include <cstdint>

#define BB 128          // batch
#define TT 64           // time steps
#define EE 300          // embed dim
#define EP 320          // padded embed dim (5 x 64)
#define HH 2048         // hidden
#define G4 8192         // 4*H

// ---------------- scratch (device globals; no allocation allowed) ----------
__device__ __half g_gxh[(size_t)TT * 128 * 128 * 64];  // [t][cb][b][gate*16+hc] fp16
__device__ __half g_w16[(size_t)G4 * HH];              // W_hh fp16
__device__ __half g_x16[(size_t)TT * BB * EP];         // gathered embeddings fp16 (padded)
__device__ __half g_wih16[(size_t)G4 * EP];            // W_ih fp16 (padded)
__device__ __half g_ha[BB * HH];                       // hidden state ping
__device__ __half g_hb[BB * HH];                       // hidden state pong
__device__ float g_c2[BB * HH];                        // cell state [cb][b][16]
__device__ unsigned g_bar;                             // persistent-kernel barrier

// single dynamic smem symbol shared by all kernels
extern __shared__ __align__(1024) char dyn_smem[];

// ---------------- helpers --------------------------------------------------
__device__ __forceinline__ uint32_t smem_u32(const void* p) {
    return (uint32_t)__cvta_generic_to_shared(p);
}
__device__ __forceinline__ void cp16(uint32_t dst, const void* src) {
    asm volatile("cp.async.cg.shared.global [%0], [%1], 16;\n" ::"r"(dst), "l"(src));
}
__device__ __forceinline__ void cp_commit() { asm volatile("cp.async.commit_group;\n"); }
template <int N> __device__ __forceinline__ void cp_wait() {
    asm volatile("cp.async.wait_group %0;\n" ::"n"(N));
}
__device__ __forceinline__ void mma_fp16(float c[4], const uint32_t a[4], uint32_t b0,
                                         uint32_t b1) {
    asm volatile(
        "mma.sync.aligned.m16n8k16.row.col.f32.f16.f16.f32 "
        "{%0,%1,%2,%3},{%4,%5,%6,%7},{%8,%9},{%0,%1,%2,%3};\n"
        : "+f"(c[0]), "+f"(c[1]), "+f"(c[2]), "+f"(c[3])
        : "r"(a[0]), "r"(a[1]), "r"(a[2]), "r"(a[3]), "r"(b0), "r"(b1));
}
__device__ __forceinline__ void ldsm4(uint32_t r[4], uint32_t addr) {
    asm volatile("ldmatrix.sync.aligned.m8n8.x4.shared.b16 {%0,%1,%2,%3}, [%4];"
                 : "=r"(r[0]), "=r"(r[1]), "=r"(r[2]), "=r"(r[3])
                 : "r"(addr));
}
__device__ __forceinline__ float sigmoidf_(float x) { return 1.0f / (1.0f + __expf(-x)); }

#define SMEM_SWZ128(x) ((x) ^ (((x) >> 3) & 0x70))

// ---------------- init / converters -----------------------------------------
__global__ void zero_kernel() {
    int i = blockIdx.x * blockDim.x + threadIdx.x;
    if (i < BB * HH) {
        g_ha[i] = __float2half(0.f);
        g_c2[i] = 0.f;
    }
    if (i == 0) g_bar = 0u;
}

__global__ void wconv_kernel(const float* __restrict__ w) {
    size_t i = ((size_t)blockIdx.x * blockDim.x + threadIdx.x) * 4;
    if (i < (size_t)G4 * HH) {
        float4 v = *reinterpret_cast<const float4*>(w + i);
        g_w16[i] = __float2half(v.x);
        g_w16[i + 1] = __float2half(v.y);
        g_w16[i + 2] = __float2half(v.z);
        g_w16[i + 3] = __float2half(v.w);
    }
}

// gather embeddings + convert w_ih to fp16 (rows padded 300 -> 320 with zeros)
__global__ void __launch_bounds__(256) gather16_kernel(const int* __restrict__ input,
                                                       const float* __restrict__ embed,
                                                       const float* __restrict__ w_ih) {
    const int wid = threadIdx.x >> 5, lane = threadIdx.x & 31;
    const int row = blockIdx.x * 8 + wid;  // 0..8191
    if (blockIdx.y == 0) {
        const int t = row >> 7, b = row & 127;
        const int tok = input[b * TT + t];
        const float* __restrict__ src = embed + (size_t)tok * EE;
        __half* __restrict__ dst = g_x16 + (size_t)row * EP;
        for (int c = lane; c < EP; c += 32)
            dst[c] = (c < EE) ? __float2half(src[c]) : __float2half(0.f);
    } else {
        const float* __restrict__ src = w_ih + (size_t)row * EE;
        __half* __restrict__ dst = g_wih16 + (size_t)row * EP;
        for (int c = lane; c < EP; c += 32)
            dst[c] = (c < EE) ? __float2half(src[c]) : __float2half(0.f);
    }
}

// ---------------- kernel 1: input projection, fp16 tensor path --------------
// grid (64, 64): BM=128 rows (1 t-slice x 128 b), BN=128 cols. 256 threads =
// 8 warps (4M x 2N), warp tile 32x64. K = 320 in 5 chunks of 64. 96 KB smem
// -> 2 CTAs/SM. Output fp16.
#define XQ_KC 64
#define XQ_NCH (EP / XQ_KC)                    // 5
#define XQ_AT (128 * 128)                      // A tile 16 KB
#define XQ_BT (128 * 128)                      // B tile 16 KB
#define XQ_STG (XQ_AT + XQ_BT)                 // 32768
#define XQ_NSTG 3
#define XQ_SMEM (XQ_NSTG * XQ_STG)             // 98304
#define XQ_THREADS 256

__global__ void __launch_bounds__(XQ_THREADS, 2) xproj16_kernel(const float* __restrict__ b_ih,
                                                                const float* __restrict__ b_hh) {
    const uint32_t sbase = smem_u32(dyn_smem);
    const int tid = threadIdx.x;
    const int wid = tid >> 5, lane = tid & 31;
    const int m0 = blockIdx.x * 128;
    const int n0 = blockIdx.y * 128;
    const int wm = (wid & 3) * 32, wn = (wid >> 2) * 64;

    const int arow = lane & 15;
    const int acs = lane >> 4;
    const int brow = (lane & 7) + ((lane & 16) >> 1);
    const int bcs = (lane >> 3) & 1;
    const int g8 = lane >> 2, tig = lane & 3;

    auto issue_stage = [&](int c, int s) {
        uint32_t base = sbase + s * XQ_STG;
        int k0 = c * XQ_KC;
#pragma unroll
        for (int i = 0; i < 4; i++) {
            int lin = tid + i * XQ_THREADS;
            int row = lin >> 3;
            int o16 = lin & 7;
            uint32_t sw = SMEM_SWZ128(row * 128 + o16 * 16);
            cp16(base + sw, &g_x16[(size_t)(m0 + row) * EP + k0 + o16 * 8]);
        }
#pragma unroll
        for (int i = 0; i < 4; i++) {
            int lin = tid + i * XQ_THREADS;
            int n = lin >> 3;
            int o16 = lin & 7;
            uint32_t sw = SMEM_SWZ128(n * 128 + o16 * 16);
            cp16(base + XQ_AT + sw, &g_wih16[(size_t)(n0 + n) * EP + k0 + o16 * 8]);
        }
        cp_commit();
    };

    float acc[2][8][4] = {};

    issue_stage(0, 0);
    issue_stage(1, 1);

    for (int kb = 0; kb < XQ_NCH; kb++) {
        cp_wait<1>();
        __syncthreads();
        int kn = kb + 2;
        if (kn < XQ_NCH) issue_stage(kn, kn % XQ_NSTG);
        else cp_commit();
        const uint32_t base = sbase + (kb % XQ_NSTG) * XQ_STG;

#pragma unroll
        for (int q = 0; q < 4; q++) {
            uint32_t a[2][4], b[4][4];
#pragma unroll
            for (int mt = 0; mt < 2; mt++) {
                int row = wm + mt * 16 + arow;
                uint32_t sw = SMEM_SWZ128(row * 128 + (2 * q + acs) * 16);
                ldsm4(a[mt], base + sw);
            }
#pragma unroll
            for (int nh = 0; nh < 4; nh++) {
                int n = wn + nh * 16 + brow;
                uint32_t sw = SMEM_SWZ128(n * 128 + (2 * q + bcs) * 16);
                ldsm4(b[nh], base + XQ_AT + sw);
            }
#pragma unroll
            for (int mt = 0; mt < 2; mt++)
#pragma unroll
                for (int nt = 0; nt < 8; nt++)
                    mma_fp16(acc[mt][nt], a[mt], b[nt >> 1][(nt & 1) * 2],
                             b[nt >> 1][(nt & 1) * 2 + 1]);
        }
    }

    // epilogue: add biases, write g_gxh[t][cb][b][gate*16+hc] as __half2 pairs
#pragma unroll
    for (int mt = 0; mt < 2; mt++) {
#pragma unroll
        for (int nt = 0; nt < 8; nt++) {
            int row0 = wm + mt * 16 + g8;
            int col0 = wn + nt * 8 + 2 * tig;
            int rg = m0 + row0;
            int t = rg >> 7, b = rg & 127;
            int j0 = n0 + col0;
            int gate = j0 >> 11;
            int qq = j0 & 2047;
            int cb = qq >> 4;
            int hc = qq & 15;
            float bias0 = b_ih[j0] + b_hh[j0];
            float bias1 = b_ih[j0 + 1] + b_hh[j0 + 1];
            size_t base0 = (((size_t)t * 128 + cb) * 128 + b) * 64 + gate * 16 + hc;
            *reinterpret_cast<__half2*>(&g_gxh[base0]) =
                __floats2half2_rn(acc[mt][nt][0] + bias0, acc[mt][nt][1] + bias1);
            size_t base2 = base0 + 8 * 64;
            *reinterpret_cast<__half2*>(&g_gxh[base2]) =
                __floats2half2_rn(acc[mt][nt][2] + bias0, acc[mt][nt][3] + bias1);
        }
    }
}

// ---------------- kernel 2: persistent fp16 LSTM (all 64 steps) -------------
// (unchanged champion)
#define KC 128
#define NCHUNK (HH / KC)                       // 16
#define ASUB_BYTES (128 * 128)                 // A sub-tile 16 KB
#define BSUB_BYTES (64 * 128)                  // B sub-tile 8 KB
#define A_BYTES (2 * ASUB_BYTES)               // 32 KB per stage
#define STG_BYTES (A_BYTES + 2 * BSUB_BYTES)   // 49152
#define NSTG 3
#define GX_OFF (NSTG * STG_BYTES)              // 147456
#define GSM_OFF (GX_OFF + 128 * 64 * 2)        // 163840
#define STEP_SMEM_BYTES (GSM_OFF + 128 * 65 * 4)  // 197120
#define STEP_THREADS 256

__global__ void __launch_bounds__(STEP_THREADS) step_persistent(float* __restrict__ d_out) {
    const uint32_t sbase = smem_u32(dyn_smem);
    const int tid = threadIdx.x;
    const int wid = tid >> 5, lane = tid & 31;
    const int cb = blockIdx.x;
    const int h0 = cb * 16;
    const int wm = (wid & 3) * 32, wn = (wid >> 2) * 32;

    const int arow = lane & 15;
    const int acs = lane >> 4;
    const int brow = (lane & 7) + ((lane & 16) >> 1);
    const int bcs = (lane >> 3) & 1;
    const int g8 = lane >> 2, tig = lane & 3;

    auto issue_w = [&](int c, int s) {
        uint32_t bb0 = sbase + s * STG_BYTES + A_BYTES;
#pragma unroll
        for (int s2 = 0; s2 < 2; s2++) {
            int k0 = c * KC + s2 * 64;
            uint32_t bbase = bb0 + s2 * BSUB_BYTES;
#pragma unroll
            for (int i = 0; i < 2; i++) {
                int lin = tid + i * STEP_THREADS;
                int n = lin >> 3;
                int o16 = lin & 7;
                int j = (n >> 4) * HH + h0 + (n & 15);
                uint32_t sw = SMEM_SWZ128(n * 128 + o16 * 16);
                cp16(bbase + sw, &g_w16[(size_t)j * HH + k0 + o16 * 8]);
            }
        }
    };
    auto issue_h = [&](const __half* h_in, int c, int s) {
        uint32_t ab0 = sbase + s * STG_BYTES;
#pragma unroll
        for (int s2 = 0; s2 < 2; s2++) {
            int k0 = c * KC + s2 * 64;
            uint32_t abase = ab0 + s2 * ASUB_BYTES;
#pragma unroll
            for (int i = 0; i < 4; i++) {
                int lin = tid + i * STEP_THREADS;
                int row = lin >> 3;
                int o16 = lin & 7;
                uint32_t sw = SMEM_SWZ128(row * 128 + o16 * 16);
                cp16(abase + sw, &h_in[row * HH + k0 + o16 * 8]);
            }
        }
    };
    auto issue_gx = [&](int t) {
        const __half* gx = &g_gxh[(((size_t)t * 128 + cb) * 128) * 64];
#pragma unroll
        for (int i = 0; i < 4; i++) {
            int lin = tid + i * STEP_THREADS;
            cp16(sbase + GX_OFF + lin * 16, gx + lin * 8);
        }
    };

    issue_w(0, 0);
    issue_gx(0);
    cp_commit();
    issue_w(1, 1);
    cp_commit();
    issue_h(g_ha, 0, 0);
    cp_commit();
    issue_h(g_ha, 1, 1);
    cp_commit();

    for (int t = 0; t < TT; t++) {
        const __half* __restrict__ h_in = (t & 1) ? g_hb : g_ha;
        __half* __restrict__ h_out = (t & 1) ? g_ha : g_hb;

        float acc[2][4][4] = {};

        for (int kb = 0; kb < NCHUNK; kb++) {
            cp_wait<1>();
            __syncthreads();
            int kn = kb + 2;
            if (kn < NCHUNK) {
                issue_h(h_in, kn, kn % NSTG);
                issue_w(kn, kn % NSTG);
            }
            cp_commit();
            const uint32_t base = sbase + (kb % NSTG) * STG_BYTES;

            uint32_t a[2][2][4], b[2][2][4];
            auto load_frags = [&](int q, int pb) {
                const int ks = q >> 2, qq = q & 3;
                const uint32_t ab = base + ks * ASUB_BYTES;
                const uint32_t bb = base + A_BYTES + ks * BSUB_BYTES;
#pragma unroll
                for (int mt = 0; mt < 2; mt++) {
                    int row = wm + mt * 16 + arow;
                    uint32_t sw = SMEM_SWZ128(row * 128 + (2 * qq + acs) * 16);
                    ldsm4(a[pb][mt], ab + sw);
                }
#pragma unroll
                for (int nh = 0; nh < 2; nh++) {
                    int n = wn + nh * 16 + brow;
                    uint32_t sw = SMEM_SWZ128(n * 128 + (2 * qq + bcs) * 16);
                    ldsm4(b[pb][nh], bb + sw);
                }
            };
            load_frags(0, 0);
#pragma unroll
            for (int q = 0; q < 8; q++) {
                if (q < 7) load_frags(q + 1, (q + 1) & 1);
                const int pb = q & 1;
#pragma unroll
                for (int mt = 0; mt < 2; mt++)
#pragma unroll
                    for (int nt = 0; nt < 4; nt++)
                        mma_fp16(acc[mt][nt], a[pb][mt], b[pb][nt >> 1][(nt & 1) * 2],
                                 b[pb][nt >> 1][(nt & 1) * 2 + 1]);
            }
        }

        float* gsm = reinterpret_cast<float*>(dyn_smem + GSM_OFF);
#pragma unroll
        for (int mt = 0; mt < 2; mt++) {
#pragma unroll
            for (int nt = 0; nt < 4; nt++) {
                int row0 = wm + mt * 16 + g8;
                int col0 = wn + nt * 8 + 2 * tig;
                gsm[row0 * 65 + col0] = acc[mt][nt][0];
                gsm[row0 * 65 + col0 + 1] = acc[mt][nt][1];
                gsm[(row0 + 8) * 65 + col0] = acc[mt][nt][2];
                gsm[(row0 + 8) * 65 + col0 + 1] = acc[mt][nt][3];
            }
        }
        __syncthreads();

        {
            const __half* __restrict__ gxs =
                reinterpret_cast<const __half*>(dyn_smem + GX_OFF);
            const int b = tid >> 1;
            const int hh = (tid & 1) * 8;
            float* __restrict__ cc = &g_c2[(cb * 128 + b) * 16 + hh];
            float4 cA = *reinterpret_cast<float4*>(cc);
            float4 cB = *reinterpret_cast<float4*>(cc + 4);
            float cv[8] = {cA.x, cA.y, cA.z, cA.w, cB.x, cB.y, cB.z, cB.w};
            __align__(16) __half hv8[8];
            float hvf[8];
#pragma unroll
            for (int i = 0; i < 8; i++) {
                int hc = hh + i;
                float xi = gsm[b * 65 + 0 * 16 + hc] + __half2float(gxs[b * 64 + 0 * 16 + hc]);
                float xf = gsm[b * 65 + 1 * 16 + hc] + __half2float(gxs[b * 64 + 1 * 16 + hc]);
                float xg = gsm[b * 65 + 2 * 16 + hc] + __half2float(gxs[b * 64 + 2 * 16 + hc]);
                float xo = gsm[b * 65 + 3 * 16 + hc] + __half2float(gxs[b * 64 + 3 * 16 + hc]);
                float ig = sigmoidf_(xi);
                float fg = sigmoidf_(xf);
                float gg = tanhf(xg);
                float og = sigmoidf_(xo);
                float cn = fg * cv[i] + ig * gg;
                cv[i] = cn;
                float hv = og * tanhf(cn);
                hvf[i] = hv;
                hv8[i] = __float2half(hv);
            }
            *reinterpret_cast<float4*>(cc) = make_float4(cv[0], cv[1], cv[2], cv[3]);
            *reinterpret_cast<float4*>(cc + 4) = make_float4(cv[4], cv[5], cv[6], cv[7]);
            *reinterpret_cast<uint4*>(&h_out[b * HH + h0 + hh]) =
                *reinterpret_cast<uint4*>(hv8);
            if (t == TT - 1) {
                *reinterpret_cast<float4*>(&d_out[b * HH + h0 + hh]) =
                    make_float4(hvf[0], hvf[1], hvf[2], hvf[3]);
                *reinterpret_cast<float4*>(&d_out[b * HH + h0 + hh + 4]) =
                    make_float4(hvf[4], hvf[5], hvf[6], hvf[7]);
            }
        }

        if (t < TT - 1) {
            __syncthreads();
            issue_w(0, 0);
            issue_gx(t + 1);
            cp_commit();
            issue_w(1, 1);
            cp_commit();
            __threadfence();
            if (tid == 0) {
                atomicAdd(&g_bar, 1u);
                const unsigned target = 128u * (unsigned)(t + 1);
                unsigned v;
                do {
                    asm volatile("ld.acquire.gpu.global.u32 %0, [%1];" : "=r"(v) : "l"(&g_bar));
                    if (v < target) __nanosleep(64);
                } while (v < target);
            }
            __syncthreads();
            issue_h(h_out, 0, 0);
            cp_commit();
            issue_h(h_out, 1, 1);
            cp_commit();
        }
    }
}

// ---------------- launch ----------------------------------------------------
extern "C" void kernel_launch(void* const* d_in, const int* in_sizes, int n_in, void* d_out,
                              int out_size) {
    const int* input = (const int*)d_in[0];
    const float* embed = (const float*)d_in[1];
    const float* w_ih = (const float*)d_in[2];
    const float* w_hh = (const float*)d_in[3];
    const float* b_ih = (const float*)d_in[4];
    const float* b_hh = (const float*)d_in[5];
    float* out = (float*)d_out;

    cudaFuncSetAttribute(xproj16_kernel, cudaFuncAttributeMaxDynamicSharedMemorySize, XQ_SMEM);
    cudaFuncSetAttribute(step_persistent, cudaFuncAttributeMaxDynamicSharedMemorySize,
                         STEP_SMEM_BYTES);

    zero_kernel<<<(BB * HH + 255) / 256, 256>>>();
    wconv_kernel<<<(int)(((size_t)G4 * HH / 4 + 255) / 256), 256>>>(w_hh);
    gather16_kernel<<<dim3(1024, 2), 256>>>(input, embed, w_ih);
    xproj16_kernel<<<dim3(64, 64), XQ_THREADS, XQ_SMEM>>>(b_ih, b_hh);
    step_persistent<<<128, STEP_THREADS, STEP_SMEM_BYTES>>>(out);
}

// round 17
// speedup vs baseline: 1.9447x; 1.0580x over previous
#include <cuda_runtime.h>
#include <cuda_fp16.h>
#include <cstdint>

#define BB 128          // batch
#define TT 64           // time steps
#define EE 300          // embed dim
#define EP 320          // padded embed dim (5 x 64)
#define HH 2048         // hidden
#define G4 8192         // 4*H

// ---------------- scratch (device globals; no allocation allowed) ----------
__device__ __half g_gxh[(size_t)TT * 128 * 128 * 64];  // [t][cb][b][gate*16+hc] fp16
__device__ __half g_w16[(size_t)G4 * HH];              // W_hh fp16
__device__ __half g_x16[(size_t)TT * BB * EP];         // gathered embeddings fp16 (padded)
__device__ __half g_wih16[(size_t)G4 * EP];            // W_ih fp16 (padded)
__device__ __half g_ha[BB * HH];                       // hidden state ping
__device__ __half g_hb[BB * HH];                       // hidden state pong
__device__ float g_c2[BB * HH];                        // cell state [cb][b][16]
__device__ unsigned g_bar;                             // persistent-kernel barrier

// single dynamic smem symbol shared by all kernels
extern __shared__ __align__(1024) char dyn_smem[];

// ---------------- helpers --------------------------------------------------
__device__ __forceinline__ uint32_t smem_u32(const void* p) {
    return (uint32_t)__cvta_generic_to_shared(p);
}
__device__ __forceinline__ void cp16(uint32_t dst, const void* src) {
    asm volatile("cp.async.cg.shared.global [%0], [%1], 16;\n" ::"r"(dst), "l"(src));
}
__device__ __forceinline__ void cp_commit() { asm volatile("cp.async.commit_group;\n"); }
template <int N> __device__ __forceinline__ void cp_wait() {
    asm volatile("cp.async.wait_group %0;\n" ::"n"(N));
}
__device__ __forceinline__ void mma_fp16(float c[4], const uint32_t a[4], uint32_t b0,
                                         uint32_t b1) {
    asm volatile(
        "mma.sync.aligned.m16n8k16.row.col.f32.f16.f16.f32 "
        "{%0,%1,%2,%3},{%4,%5,%6,%7},{%8,%9},{%0,%1,%2,%3};\n"
        : "+f"(c[0]), "+f"(c[1]), "+f"(c[2]), "+f"(c[3])
        : "r"(a[0]), "r"(a[1]), "r"(a[2]), "r"(a[3]), "r"(b0), "r"(b1));
}
__device__ __forceinline__ void ldsm4(uint32_t r[4], uint32_t addr) {
    asm volatile("ldmatrix.sync.aligned.m8n8.x4.shared.b16 {%0,%1,%2,%3}, [%4];"
                 : "=r"(r[0]), "=r"(r[1]), "=r"(r[2]), "=r"(r[3])
                 : "r"(addr));
}
__device__ __forceinline__ float tanh_fast(float x) {
    float r;
    asm("tanh.approx.f32 %0, %1;" : "=f"(r) : "f"(x));
    return r;
}
__device__ __forceinline__ float sigmoid_fast(float x) {
    return fmaf(0.5f, tanh_fast(0.5f * x), 0.5f);
}

#define SMEM_SWZ128(x) ((x) ^ (((x) >> 3) & 0x70))

// ---------------- init / converters -----------------------------------------
__global__ void wconv_kernel(const float* __restrict__ w) {
    size_t i = ((size_t)blockIdx.x * blockDim.x + threadIdx.x) * 4;
    if (i < (size_t)G4 * HH) {
        float4 v = *reinterpret_cast<const float4*>(w + i);
        g_w16[i] = __float2half(v.x);
        g_w16[i + 1] = __float2half(v.y);
        g_w16[i + 2] = __float2half(v.z);
        g_w16[i + 3] = __float2half(v.w);
    }
}

// gather embeddings + convert w_ih to fp16 (rows padded 300 -> 320 with zeros)
// blockIdx.y == 2 lane handles state zeroing (fused former zero_kernel).
__global__ void __launch_bounds__(256) gather16_kernel(const int* __restrict__ input,
                                                       const float* __restrict__ embed,
                                                       const float* __restrict__ w_ih) {
    if (blockIdx.y == 2) {
        int i = blockIdx.x * blockDim.x + threadIdx.x;
        if (i < BB * HH) {
            g_ha[i] = __float2half(0.f);
            g_c2[i] = 0.f;
        }
        if (i == 0) g_bar = 0u;
        return;
    }
    const int wid = threadIdx.x >> 5, lane = threadIdx.x & 31;
    const int row = blockIdx.x * 8 + wid;  // 0..8191
    if (row >= 8192) return;
    if (blockIdx.y == 0) {
        const int t = row >> 7, b = row & 127;
        const int tok = input[b * TT + t];
        const float* __restrict__ src = embed + (size_t)tok * EE;
        __half* __restrict__ dst = g_x16 + (size_t)row * EP;
        for (int c = lane; c < EP; c += 32)
            dst[c] = (c < EE) ? __float2half(src[c]) : __float2half(0.f);
    } else {
        const float* __restrict__ src = w_ih + (size_t)row * EE;
        __half* __restrict__ dst = g_wih16 + (size_t)row * EP;
        for (int c = lane; c < EP; c += 32)
            dst[c] = (c < EE) ? __float2half(src[c]) : __float2half(0.f);
    }
}

// ---------------- kernel 1: input projection, fp16 tensor path --------------
// grid (64, 64): BM=128, BN=128. 256 threads = 8 warps (4M x 2N), warp tile
// 32x64. K = 320 in 5 chunks of 64. 96 KB smem -> 2 CTAs/SM. Output fp16.
#define XQ_KC 64
#define XQ_NCH (EP / XQ_KC)                    // 5
#define XQ_AT (128 * 128)                      // A tile 16 KB
#define XQ_BT (128 * 128)                      // B tile 16 KB
#define XQ_STG (XQ_AT + XQ_BT)                 // 32768
#define XQ_NSTG 3
#define XQ_SMEM (XQ_NSTG * XQ_STG)             // 98304
#define XQ_THREADS 256

__global__ void __launch_bounds__(XQ_THREADS, 2) xproj16_kernel(const float* __restrict__ b_ih,
                                                                const float* __restrict__ b_hh) {
    const uint32_t sbase = smem_u32(dyn_smem);
    const int tid = threadIdx.x;
    const int wid = tid >> 5, lane = tid & 31;
    const int m0 = blockIdx.x * 128;
    const int n0 = blockIdx.y * 128;
    const int wm = (wid & 3) * 32, wn = (wid >> 2) * 64;

    const int arow = lane & 15;
    const int acs = lane >> 4;
    const int brow = (lane & 7) + ((lane & 16) >> 1);
    const int bcs = (lane >> 3) & 1;
    const int g8 = lane >> 2, tig = lane & 3;

    auto issue_stage = [&](int c, int s) {
        uint32_t base = sbase + s * XQ_STG;
        int k0 = c * XQ_KC;
#pragma unroll
        for (int i = 0; i < 4; i++) {
            int lin = tid + i * XQ_THREADS;
            int row = lin >> 3;
            int o16 = lin & 7;
            uint32_t sw = SMEM_SWZ128(row * 128 + o16 * 16);
            cp16(base + sw, &g_x16[(size_t)(m0 + row) * EP + k0 + o16 * 8]);
        }
#pragma unroll
        for (int i = 0; i < 4; i++) {
            int lin = tid + i * XQ_THREADS;
            int n = lin >> 3;
            int o16 = lin & 7;
            uint32_t sw = SMEM_SWZ128(n * 128 + o16 * 16);
            cp16(base + XQ_AT + sw, &g_wih16[(size_t)(n0 + n) * EP + k0 + o16 * 8]);
        }
        cp_commit();
    };

    float acc[2][8][4] = {};

    issue_stage(0, 0);
    issue_stage(1, 1);

    for (int kb = 0; kb < XQ_NCH; kb++) {
        cp_wait<1>();
        __syncthreads();
        int kn = kb + 2;
        if (kn < XQ_NCH) issue_stage(kn, kn % XQ_NSTG);
        else cp_commit();
        const uint32_t base = sbase + (kb % XQ_NSTG) * XQ_STG;

#pragma unroll
        for (int q = 0; q < 4; q++) {
            uint32_t a[2][4], b[4][4];
#pragma unroll
            for (int mt = 0; mt < 2; mt++) {
                int row = wm + mt * 16 + arow;
                uint32_t sw = SMEM_SWZ128(row * 128 + (2 * q + acs) * 16);
                ldsm4(a[mt], base + sw);
            }
#pragma unroll
            for (int nh = 0; nh < 4; nh++) {
                int n = wn + nh * 16 + brow;
                uint32_t sw = SMEM_SWZ128(n * 128 + (2 * q + bcs) * 16);
                ldsm4(b[nh], base + XQ_AT + sw);
            }
#pragma unroll
            for (int mt = 0; mt < 2; mt++)
#pragma unroll
                for (int nt = 0; nt < 8; nt++)
                    mma_fp16(acc[mt][nt], a[mt], b[nt >> 1][(nt & 1) * 2],
                             b[nt >> 1][(nt & 1) * 2 + 1]);
        }
    }

    // epilogue: add biases, write g_gxh[t][cb][b][gate*16+hc] as __half2 pairs
#pragma unroll
    for (int mt = 0; mt < 2; mt++) {
#pragma unroll
        for (int nt = 0; nt < 8; nt++) {
            int row0 = wm + mt * 16 + g8;
            int col0 = wn + nt * 8 + 2 * tig;
            int rg = m0 + row0;
            int t = rg >> 7, b = rg & 127;
            int j0 = n0 + col0;
            int gate = j0 >> 11;
            int qq = j0 & 2047;
            int cb = qq >> 4;
            int hc = qq & 15;
            float bias0 = b_ih[j0] + b_hh[j0];
            float bias1 = b_ih[j0 + 1] + b_hh[j0 + 1];
            size_t base0 = (((size_t)t * 128 + cb) * 128 + b) * 64 + gate * 16 + hc;
            *reinterpret_cast<__half2*>(&g_gxh[base0]) =
                __floats2half2_rn(acc[mt][nt][0] + bias0, acc[mt][nt][1] + bias1);
            size_t base2 = base0 + 8 * 64;
            *reinterpret_cast<__half2*>(&g_gxh[base2]) =
                __floats2half2_rn(acc[mt][nt][2] + bias0, acc[mt][nt][3] + bias1);
        }
    }
}

// ---------------- kernel 2: persistent fp16 LSTM (all 64 steps) -------------
// champion structure; cell uses tanh.approx transcendentals
#define KC 128
#define NCHUNK (HH / KC)                       // 16
#define ASUB_BYTES (128 * 128)                 // A sub-tile 16 KB
#define BSUB_BYTES (64 * 128)                  // B sub-tile 8 KB
#define A_BYTES (2 * ASUB_BYTES)               // 32 KB per stage
#define STG_BYTES (A_BYTES + 2 * BSUB_BYTES)   // 49152
#define NSTG 3
#define GX_OFF (NSTG * STG_BYTES)              // 147456
#define GSM_OFF (GX_OFF + 128 * 64 * 2)        // 163840
#define STEP_SMEM_BYTES (GSM_OFF + 128 * 65 * 4)  // 197120
#define STEP_THREADS 256

__global__ void __launch_bounds__(STEP_THREADS) step_persistent(float* __restrict__ d_out) {
    const uint32_t sbase = smem_u32(dyn_smem);
    const int tid = threadIdx.x;
    const int wid = tid >> 5, lane = tid & 31;
    const int cb = blockIdx.x;
    const int h0 = cb * 16;
    const int wm = (wid & 3) * 32, wn = (wid >> 2) * 32;

    const int arow = lane & 15;
    const int acs = lane >> 4;
    const int brow = (lane & 7) + ((lane & 16) >> 1);
    const int bcs = (lane >> 3) & 1;
    const int g8 = lane >> 2, tig = lane & 3;

    auto issue_w = [&](int c, int s) {
        uint32_t bb0 = sbase + s * STG_BYTES + A_BYTES;
#pragma unroll
        for (int s2 = 0; s2 < 2; s2++) {
            int k0 = c * KC + s2 * 64;
            uint32_t bbase = bb0 + s2 * BSUB_BYTES;
#pragma unroll
            for (int i = 0; i < 2; i++) {
                int lin = tid + i * STEP_THREADS;
                int n = lin >> 3;
                int o16 = lin & 7;
                int j = (n >> 4) * HH + h0 + (n & 15);
                uint32_t sw = SMEM_SWZ128(n * 128 + o16 * 16);
                cp16(bbase + sw, &g_w16[(size_t)j * HH + k0 + o16 * 8]);
            }
        }
    };
    auto issue_h = [&](const __half* h_in, int c, int s) {
        uint32_t ab0 = sbase + s * STG_BYTES;
#pragma unroll
        for (int s2 = 0; s2 < 2; s2++) {
            int k0 = c * KC + s2 * 64;
            uint32_t abase = ab0 + s2 * ASUB_BYTES;
#pragma unroll
            for (int i = 0; i < 4; i++) {
                int lin = tid + i * STEP_THREADS;
                int row = lin >> 3;
                int o16 = lin & 7;
                uint32_t sw = SMEM_SWZ128(row * 128 + o16 * 16);
                cp16(abase + sw, &h_in[row * HH + k0 + o16 * 8]);
            }
        }
    };
    auto issue_gx = [&](int t) {
        const __half* gx = &g_gxh[(((size_t)t * 128 + cb) * 128) * 64];
#pragma unroll
        for (int i = 0; i < 4; i++) {
            int lin = tid + i * STEP_THREADS;
            cp16(sbase + GX_OFF + lin * 16, gx + lin * 8);
        }
    };

    issue_w(0, 0);
    issue_gx(0);
    cp_commit();
    issue_w(1, 1);
    cp_commit();
    issue_h(g_ha, 0, 0);
    cp_commit();
    issue_h(g_ha, 1, 1);
    cp_commit();

    for (int t = 0; t < TT; t++) {
        const __half* __restrict__ h_in = (t & 1) ? g_hb : g_ha;
        __half* __restrict__ h_out = (t & 1) ? g_ha : g_hb;

        float acc[2][4][4] = {};

        for (int kb = 0; kb < NCHUNK; kb++) {
            cp_wait<1>();
            __syncthreads();
            int kn = kb + 2;
            if (kn < NCHUNK) {
                issue_h(h_in, kn, kn % NSTG);
                issue_w(kn, kn % NSTG);
            }
            cp_commit();
            const uint32_t base = sbase + (kb % NSTG) * STG_BYTES;

            uint32_t a[2][2][4], b[2][2][4];
            auto load_frags = [&](int q, int pb) {
                const int ks = q >> 2, qq = q & 3;
                const uint32_t ab = base + ks * ASUB_BYTES;
                const uint32_t bb = base + A_BYTES + ks * BSUB_BYTES;
#pragma unroll
                for (int mt = 0; mt < 2; mt++) {
                    int row = wm + mt * 16 + arow;
                    uint32_t sw = SMEM_SWZ128(row * 128 + (2 * qq + acs) * 16);
                    ldsm4(a[pb][mt], ab + sw);
                }
#pragma unroll
                for (int nh = 0; nh < 2; nh++) {
                    int n = wn + nh * 16 + brow;
                    uint32_t sw = SMEM_SWZ128(n * 128 + (2 * qq + bcs) * 16);
                    ldsm4(b[pb][nh], bb + sw);
                }
            };
            load_frags(0, 0);
#pragma unroll
            for (int q = 0; q < 8; q++) {
                if (q < 7) load_frags(q + 1, (q + 1) & 1);
                const int pb = q & 1;
#pragma unroll
                for (int mt = 0; mt < 2; mt++)
#pragma unroll
                    for (int nt = 0; nt < 4; nt++)
                        mma_fp16(acc[mt][nt], a[pb][mt], b[pb][nt >> 1][(nt & 1) * 2],
                                 b[pb][nt >> 1][(nt & 1) * 2 + 1]);
            }
        }

        float* gsm = reinterpret_cast<float*>(dyn_smem + GSM_OFF);
#pragma unroll
        for (int mt = 0; mt < 2; mt++) {
#pragma unroll
            for (int nt = 0; nt < 4; nt++) {
                int row0 = wm + mt * 16 + g8;
                int col0 = wn + nt * 8 + 2 * tig;
                gsm[row0 * 65 + col0] = acc[mt][nt][0];
                gsm[row0 * 65 + col0 + 1] = acc[mt][nt][1];
                gsm[(row0 + 8) * 65 + col0] = acc[mt][nt][2];
                gsm[(row0 + 8) * 65 + col0 + 1] = acc[mt][nt][3];
            }
        }
        __syncthreads();

        {
            const __half* __restrict__ gxs =
                reinterpret_cast<const __half*>(dyn_smem + GX_OFF);
            const int b = tid >> 1;
            const int hh = (tid & 1) * 8;
            float* __restrict__ cc = &g_c2[(cb * 128 + b) * 16 + hh];
            float4 cA = *reinterpret_cast<float4*>(cc);
            float4 cB = *reinterpret_cast<float4*>(cc + 4);
            float cv[8] = {cA.x, cA.y, cA.z, cA.w, cB.x, cB.y, cB.z, cB.w};
            __align__(16) __half hv8[8];
            float hvf[8];
#pragma unroll
            for (int i = 0; i < 8; i++) {
                int hc = hh + i;
                float xi = gsm[b * 65 + 0 * 16 + hc] + __half2float(gxs[b * 64 + 0 * 16 + hc]);
                float xf = gsm[b * 65 + 1 * 16 + hc] + __half2float(gxs[b * 64 + 1 * 16 + hc]);
                float xg = gsm[b * 65 + 2 * 16 + hc] + __half2float(gxs[b * 64 + 2 * 16 + hc]);
                float xo = gsm[b * 65 + 3 * 16 + hc] + __half2float(gxs[b * 64 + 3 * 16 + hc]);
                float ig = sigmoid_fast(xi);
                float fg = sigmoid_fast(xf);
                float gg = tanh_fast(xg);
                float og = sigmoid_fast(xo);
                float cn = fg * cv[i] + ig * gg;
                cv[i] = cn;
                float hv = og * tanh_fast(cn);
                hvf[i] = hv;
                hv8[i] = __float2half(hv);
            }
            *reinterpret_cast<float4*>(cc) = make_float4(cv[0], cv[1], cv[2], cv[3]);
            *reinterpret_cast<float4*>(cc + 4) = make_float4(cv[4], cv[5], cv[6], cv[7]);
            *reinterpret_cast<uint4*>(&h_out[b * HH + h0 + hh]) =
                *reinterpret_cast<uint4*>(hv8);
            if (t == TT - 1) {
                *reinterpret_cast<float4*>(&d_out[b * HH + h0 + hh]) =
                    make_float4(hvf[0], hvf[1], hvf[2], hvf[3]);
                *reinterpret_cast<float4*>(&d_out[b * HH + h0 + hh + 4]) =
                    make_float4(hvf[4], hvf[5], hvf[6], hvf[7]);
            }
        }

        if (t < TT - 1) {
            __syncthreads();
            issue_w(0, 0);
            issue_gx(t + 1);
            cp_commit();
            issue_w(1, 1);
            cp_commit();
            __threadfence();
            if (tid == 0) {
                atomicAdd(&g_bar, 1u);
                const unsigned target = 128u * (unsigned)(t + 1);
                unsigned v;
                do {
                    asm volatile("ld.acquire.gpu.global.u32 %0, [%1];" : "=r"(v) : "l"(&g_bar));
                    if (v < target) __nanosleep(64);
                } while (v < target);
            }
            __syncthreads();
            issue_h(h_out, 0, 0);
            cp_commit();
            issue_h(h_out, 1, 1);
            cp_commit();
        }
    }
}

// ---------------- launch ----------------------------------------------------
extern "C" void kernel_launch(void* const* d_in, const int* in_sizes, int n_in, void* d_out,
                              int out_size) {
    const int* input = (const int*)d_in[0];
    const float* embed = (const float*)d_in[1];
    const float* w_ih = (const float*)d_in[2];
    const float* w_hh = (const float*)d_in[3];
    const float* b_ih = (const float*)d_in[4];
    const float* b_hh = (const float*)d_in[5];
    float* out = (float*)d_out;

    cudaFuncSetAttribute(xproj16_kernel, cudaFuncAttributeMaxDynamicSharedMemorySize, XQ_SMEM);
    cudaFuncSetAttribute(step_persistent, cudaFuncAttributeMaxDynamicSharedMemorySize,
                         STEP_SMEM_BYTES);

    wconv_kernel<<<(int)(((size_t)G4 * HH / 4 + 255) / 256), 256>>>(w_hh);
    gather16_kernel<<<dim3(1024, 3), 256>>>(input, embed, w_ih);
    xproj16_kernel<<<dim3(64, 64), XQ_THREADS, XQ_SMEM>>>(b_ih, b_hh);
    step_persistent<<<128, STEP_THREADS, STEP_SMEM_BYTES>>>(out);
}